// round 2
// baseline (speedup 1.0000x reference)
#include <cuda_runtime.h>

// ---------------- problem constants ----------------
constexpr int B_   = 2;
constexpr int C_   = 256;
constexpr int Hh   = 48;
constexpr int Ww   = 48;
constexpr int H3   = 144;            // 3*48 sampled grid
constexpr int HO   = 142, WO = 142;  // VALID 3x3 conv output
constexpr int NPB  = HO * WO;        // 20164
constexpr int NTOT = B_ * NPB;       // 40328
constexpr int KK   = C_ * 9;         // 2304
constexpr int PLANE3 = H3 * H3;      // 20736
constexpr int NA   = 5;              // angles
constexpr int NQ   = NPB / 4;        // 5041 (NPB divisible by 4)

// ---------------- static scratch (no runtime allocation allowed) ----------------
__device__ float g_xo[NA * B_ * C_ * PLANE3];   // ~212 MB sampled branches
__device__ float g_y0[B_ * C_ * NPB];           // identity branch conv output
__device__ float g_feas[4 * B_ * C_ * NPB];     // BN+ReLU branches 1..4
__device__ float g_fsum[B_ * C_];               // channel sums for GAP
__device__ float g_att[B_ * 4 * C_];            // softmax attention

// ---------------- angle offset tables (match numpy double->float rounding) ----------------
#define S2  1.4142135623730951
#define S2H 0.7071067811865476

__constant__ float c_ox[45] = {
    // angle 0
    0.f,0.f,0.f,0.f,0.f,0.f,0.f,0.f,0.f,
    // angle 45
    (float)(1.0-S2), (float)(1.0-S2H), 1.f, (float)(-S2H), 0.f, (float)(S2H),
    -1.f, (float)(S2H-1.0), (float)(S2-1.0),
    // angle 90
    0.f,1.f,2.f,-1.f,0.f,1.f,-2.f,-1.f,0.f,
    // angle 135
    1.f, (float)(1.0+S2H), (float)(1.0+S2), (float)(-S2H), 0.f, (float)(S2H),
    (float)(-1.0-S2), (float)(-1.0-S2H), -1.f,
    // angle 180
    2.f,2.f,2.f,0.f,0.f,0.f,-2.f,-2.f,-2.f
};
__constant__ float c_oy[45] = {
    // angle 0
    0.f,0.f,0.f,0.f,0.f,0.f,0.f,0.f,0.f,
    // angle 45
    1.f, (float)(S2H), (float)(S2-1.0), (float)(1.0-S2H), 0.f, (float)(S2H-1.0),
    (float)(1.0-S2), (float)(-S2H), -1.f,
    // angle 90
    2.f,1.f,0.f,1.f,0.f,-1.f,0.f,-1.f,-2.f,
    // angle 135
    (float)(1.0+S2), (float)(S2H), -1.f, (float)(1.0+S2H), 0.f, (float)(-1.0-S2H),
    1.f, (float)(-S2H), (float)(1.0+S2),
    // angle 180
    2.f,0.f,-2.f,2.f,0.f,-2.f,2.f,0.f,-2.f
};
// (ki*144 + kj) for k = ki*3+kj
__constant__ int c_off9[9] = {0, 1, 2, 144, 145, 146, 288, 289, 290};

// ---------------- 1) bilinear resample, all 5 angles ----------------
__global__ void sample_kernel(const float* __restrict__ x) {
    int idx = blockIdx.x * blockDim.x + threadIdx.x;
    const int total = NA * B_ * C_ * PLANE3;   // 53,084,160 < 2^31
    if (idx >= total) return;

    int cc = idx % H3;  int t = idx / H3;
    int r  = t % H3;    t /= H3;
    int c  = t % C_;    t /= C_;
    int bb = t % B_;    int a = t / B_;

    int i = r / 3, ki = r % 3;
    int j = cc / 3, kj = cc % 3;
    int k = ki * 3 + kj;

    // px = p0 + (pn + ox): keep jax op order
    float sx = (float)(ki - 1) + c_ox[a * 9 + k];
    float sy = (float)(kj - 1) + c_oy[a * 9 + k];
    float px = (float)(i + 1) + sx;
    float py = (float)(j + 1) + sy;

    float fx = floorf(px), fy = floorf(py);
    const float HI = 49.f;   // Hp-1 (padded 50x50)
    float ltx = fminf(fmaxf(fx,        0.f), HI);
    float lty = fminf(fmaxf(fy,        0.f), HI);
    float rbx = fminf(fmaxf(fx + 1.f,  0.f), HI);
    float rby = fminf(fmaxf(fy + 1.f,  0.f), HI);
    float pxc = fminf(fmaxf(px,        0.f), HI);
    float pyc = fminf(fmaxf(py,        0.f), HI);

    float g_lt = (1.f + (ltx - pxc)) * (1.f + (lty - pyc));
    float g_rb = (1.f - (rbx - pxc)) * (1.f - (rby - pyc));
    float g_lb = (1.f + (ltx - pxc)) * (1.f - (rby - pyc));
    float g_rt = (1.f - (rbx - pxc)) * (1.f + (lty - pyc));

    int ix0 = (int)ltx, iy0 = (int)lty, ix1 = (int)rbx, iy1 = (int)rby;

    const float* xp = x + (bb * C_ + c) * (Hh * Ww);
    // padded coord -> raw x coord with zero border
    auto gat = [&](int ix, int iy) -> float {
        ix -= 1; iy -= 1;
        if (ix < 0 || ix >= Hh || iy < 0 || iy >= Ww) return 0.f;
        return xp[ix * Ww + iy];
    };

    float v = g_lt * gat(ix0, iy0) + g_rb * gat(ix1, iy1)
            + g_lb * gat(ix0, iy1) + g_rt * gat(ix1, iy0);

    g_xo[((a * B_ + bb) * C_ + c) * PLANE3 + r * H3 + cc] = v;
}

// ---------------- 2) implicit-GEMM conv + fused BN/ReLU epilogue ----------------
// C[co][n] = sum_k W[co][k] * XO[a][bb(n)][ci(k)][u(n)+ki(k)][v(n)+kj(k)]
// Tile: 128(co) x 128(n) x 8(k), 256 threads, 8x8 micro-tile.
__global__ void __launch_bounds__(256, 2)
conv_kernel(const float* __restrict__ w,
            const float* __restrict__ gma, const float* __restrict__ bta,
            const float* __restrict__ mu,  const float* __restrict__ var) {
    const int a      = blockIdx.z;
    const int coBase = blockIdx.y * 128;
    const int nBase  = blockIdx.x * 128;
    const int t      = threadIdx.x;

    __shared__ float As[8][128];
    __shared__ float Bs[8][132];   // +4 pad (keeps 16B alignment: 132%4==0)

    float acc[8][8];
#pragma unroll
    for (int i = 0; i < 8; i++)
#pragma unroll
        for (int j = 0; j < 8; j++) acc[i][j] = 0.f;

    // ---- B-load mapping: 8 k-slots x 32 threads x 4 consecutive n ----
    const int bk  = t >> 5;
    const int bn0 = (t & 31) << 2;
    int  preOff[4];
    bool nOk[4];
#pragma unroll
    for (int q = 0; q < 4; q++) {
        int n  = nBase + bn0 + q;
        nOk[q] = (n < NTOT);
        int n2 = nOk[q] ? n : 0;
        int bb = n2 / NPB;
        int p  = n2 - bb * NPB;
        int u  = p / WO, v = p - u * WO;
        preOff[q] = ((a * B_ + bb) * C_) * PLANE3 + u * H3 + v;
    }
    // ---- A-load mapping: 128 co x 2 half-rows of 4 k ----
    const int am = t >> 1;
    const int ak = (t & 1) << 2;
    const float* wrow = w + (coBase + am) * KK + ak;

    const int mrow = (t >> 4) << 3;
    const int ncol = (t & 15) << 3;

    for (int kt = 0; kt < KK; kt += 8) {
        float4 av = *(const float4*)(wrow + kt);
        As[ak + 0][am] = av.x; As[ak + 1][am] = av.y;
        As[ak + 2][am] = av.z; As[ak + 3][am] = av.w;

        int k   = kt + bk;
        int ci  = k / 9;
        int r9  = k - ci * 9;
        int off = ci * PLANE3 + c_off9[r9];
        float4 bv;
        bv.x = nOk[0] ? g_xo[off + preOff[0]] : 0.f;
        bv.y = nOk[1] ? g_xo[off + preOff[1]] : 0.f;
        bv.z = nOk[2] ? g_xo[off + preOff[2]] : 0.f;
        bv.w = nOk[3] ? g_xo[off + preOff[3]] : 0.f;
        *(float4*)&Bs[bk][bn0] = bv;
        __syncthreads();

#pragma unroll
        for (int kk = 0; kk < 8; kk++) {
            float af[8], bf[8];
            *(float4*)&af[0] = *(const float4*)&As[kk][mrow];
            *(float4*)&af[4] = *(const float4*)&As[kk][mrow + 4];
            *(float4*)&bf[0] = *(const float4*)&Bs[kk][ncol];
            *(float4*)&bf[4] = *(const float4*)&Bs[kk][ncol + 4];
#pragma unroll
            for (int i = 0; i < 8; i++)
#pragma unroll
                for (int j = 0; j < 8; j++)
                    acc[i][j] = fmaf(af[i], bf[j], acc[i][j]);
        }
        __syncthreads();
    }

    // ---- epilogue: angle 0 -> y0, angles 1..4 -> BN(eval)+ReLU -> feas ----
#pragma unroll
    for (int i = 0; i < 8; i++) {
        int co = coBase + mrow + i;
        float sc = 1.f, sh = 0.f;
        if (a > 0) {
            int br = a - 1;
            float g  = gma[br * C_ + co];
            float be = bta[br * C_ + co];
            float m  = mu [br * C_ + co];
            float vv = var[br * C_ + co];
            sc = g / sqrtf(vv + 1e-5f);
            sh = be - m * sc;
        }
#pragma unroll
        for (int j = 0; j < 8; j++) {
            int n = nBase + ncol + j;
            if (n >= NTOT) continue;
            int bb = n / NPB;
            int p  = n - bb * NPB;
            float vout = acc[i][j];
            if (a == 0) {
                g_y0[(bb * C_ + co) * NPB + p] = vout;
            } else {
                vout = fmaxf(fmaf(vout, sc, sh), 0.f);
                g_feas[(((a - 1) * B_ + bb) * C_ + co) * NPB + p] = vout;
            }
        }
    }
}

// ---------------- 3) per-(b,c) sum of feas over 4 branches and H'W' ----------------
__global__ void reduce_kernel() {
    int bc = blockIdx.x;   // 0..511  (= bb*C_ + c)
    float s = 0.f;
    for (int m = 0; m < 4; m++) {
        const float4* p = (const float4*)&g_feas[(m * B_ * C_ + bc) * NPB];
        for (int i = threadIdx.x; i < NQ; i += 256) {
            float4 v = p[i];
            s += (v.x + v.y) + (v.z + v.w);
        }
    }
    __shared__ float sm[256];
    sm[threadIdx.x] = s;
    __syncthreads();
    for (int st = 128; st > 0; st >>= 1) {
        if (threadIdx.x < st) sm[threadIdx.x] += sm[threadIdx.x + st];
        __syncthreads();
    }
    if (threadIdx.x == 0) g_fsum[bc] = sm[0];
}

// ---------------- 4) attention: GAP -> fc1 -> fc2 -> softmax over branches ----------------
__global__ void att_kernel(const float* __restrict__ fc1w, const float* __restrict__ fc1b,
                           const float* __restrict__ fc2w, const float* __restrict__ fc2b) {
    __shared__ float s_fs[B_ * C_];
    __shared__ float s_z[B_ * 32];
    __shared__ float s_att[B_ * 4 * C_];
    int t = threadIdx.x;

    for (int i = t; i < B_ * C_; i += 256)
        s_fs[i] = g_fsum[i] * (1.f / (float)NPB);
    __syncthreads();

    if (t < 64) {   // fea_z[b][d] = fea_s[b] . fc1_w[d] + fc1_b[d]
        int b = t >> 5, d = t & 31;
        float s = fc1b[d];
        for (int c = 0; c < C_; c++) s += s_fs[b * C_ + c] * fc1w[d * C_ + c];
        s_z[b * 32 + d] = s;
    }
    __syncthreads();

    for (int i = t; i < B_ * 4 * C_; i += 256) {   // att[b][m][c]
        int c = i % C_; int bm = i / C_; int m = bm % 4; int b = bm / 4;
        float s = fc2b[m * C_ + c];
        const float* wr = fc2w + (m * C_ + c) * 32;
#pragma unroll
        for (int d = 0; d < 32; d++) s += s_z[b * 32 + d] * wr[d];
        s_att[(b * 4 + m) * C_ + c] = s;
    }
    __syncthreads();

    for (int i = t; i < B_ * C_; i += 256) {   // softmax over m
        int b = i / C_, c = i % C_;
        float a0 = s_att[(b * 4 + 0) * C_ + c];
        float a1 = s_att[(b * 4 + 1) * C_ + c];
        float a2 = s_att[(b * 4 + 2) * C_ + c];
        float a3 = s_att[(b * 4 + 3) * C_ + c];
        float mx = fmaxf(fmaxf(a0, a1), fmaxf(a2, a3));
        float e0 = expf(a0 - mx), e1 = expf(a1 - mx), e2 = expf(a2 - mx), e3 = expf(a3 - mx);
        float inv = 1.f / (e0 + e1 + e2 + e3);
        g_att[(b * 4 + 0) * C_ + c] = e0 * inv;
        g_att[(b * 4 + 1) * C_ + c] = e1 * inv;
        g_att[(b * 4 + 2) * C_ + c] = e2 * inv;
        g_att[(b * 4 + 3) * C_ + c] = e3 * inv;
    }
}

// ---------------- 5) fea_v = sum_m feas_m * att_m + y0 ----------------
__global__ void final_kernel(float* __restrict__ out) {
    int idx = blockIdx.x * blockDim.x + threadIdx.x;
    const int total = B_ * C_ * NQ;
    if (idx >= total) return;
    int pq = idx % NQ;
    int bc = idx / NQ;
    int c  = bc % C_, b = bc / C_;

    float4 o = ((const float4*)&g_y0[bc * NPB])[pq];
#pragma unroll
    for (int m = 0; m < 4; m++) {
        float wm = g_att[(b * 4 + m) * C_ + c];
        float4 f = ((const float4*)&g_feas[(m * B_ * C_ + bc) * NPB])[pq];
        o.x = fmaf(f.x, wm, o.x);
        o.y = fmaf(f.y, wm, o.y);
        o.z = fmaf(f.z, wm, o.z);
        o.w = fmaf(f.w, wm, o.w);
    }
    ((float4*)out)[idx] = o;
}

// ---------------- launch ----------------
extern "C" void kernel_launch(void* const* d_in, const int* in_sizes, int n_in,
                              void* d_out, int out_size) {
    const float* x    = (const float*)d_in[0];
    const float* w    = (const float*)d_in[1];
    const float* gma  = (const float*)d_in[2];
    const float* bta  = (const float*)d_in[3];
    const float* mu   = (const float*)d_in[4];
    const float* var  = (const float*)d_in[5];
    const float* fc1w = (const float*)d_in[6];
    const float* fc1b = (const float*)d_in[7];
    const float* fc2w = (const float*)d_in[8];
    const float* fc2b = (const float*)d_in[9];
    float* out = (float*)d_out;

    const int totS = NA * B_ * C_ * PLANE3;
    sample_kernel<<<(totS + 255) / 256, 256>>>(x);

    dim3 grid((NTOT + 127) / 128, C_ / 128, NA);
    conv_kernel<<<grid, 256>>>(w, gma, bta, mu, var);

    reduce_kernel<<<B_ * C_, 256>>>();
    att_kernel<<<1, 256>>>(fc1w, fc1b, fc2w, fc2b);
    final_kernel<<<(B_ * C_ * NQ + 255) / 256, 256>>>(out);
}

// round 4
// speedup vs baseline: 1.9653x; 1.9653x over previous
#include <cuda_runtime.h>
#include <cuda_bf16.h>
#include <cstdint>

// ---------------- problem constants ----------------
constexpr int B_   = 2;
constexpr int C_   = 256;
constexpr int Hh   = 48;
constexpr int Ww   = 48;
constexpr int H3   = 144;            // 3*48 sampled grid
constexpr int HO   = 142, WO = 142;  // VALID 3x3 conv output
constexpr int NPB  = HO * WO;        // 20164
constexpr int NTOT = B_ * NPB;       // 40328
constexpr int KK   = C_ * 9;         // 2304
constexpr int PLANE3 = H3 * H3;      // 20736
constexpr int NA   = 5;              // angles
constexpr int NQ   = NPB / 4;        // 5041

// conv-GEMM tiling (mma.sync path, sm_100 non-'a' safe)
constexpr int TILE_M = 128;
constexpr int TILE_N = 128;
constexpr int CHUNK  = 32;                  // k per chunk (2 ksteps of 16)
constexpr int NCHUNK = KK / CHUNK;          // 72
constexpr int NTILES = (NTOT + TILE_N - 1) / TILE_N;   // 316

// smem: per stage, 4 operand planes (A hi/lo, B hi/lo), each 2 ksteps x 128 rows x 48B
constexpr int ROWB   = 48;                  // 32B payload + 16B pad (ldmatrix conflict-free)
constexpr int KSTEPB = 128 * ROWB;          // 6144
constexpr int OFF_AH = 0;
constexpr int OFF_AL = 2 * KSTEPB;          // 12288
constexpr int OFF_BH = 4 * KSTEPB;          // 24576
constexpr int OFF_BL = 6 * KSTEPB;          // 36864
constexpr int STAGE  = 8 * KSTEPB;          // 49152
constexpr int SMEM_TOTAL = 2 * STAGE;       // 98304

// ---------------- static scratch ----------------
__device__ __align__(16) unsigned g_xoP[NA * B_ * C_ * PLANE3];  // packed hi|lo<<16 bf16
__device__ __align__(16) unsigned g_wP[C_ * KK];                 // packed weights
__device__ int   g_koff[KK];
__device__ __align__(16) float g_y0[B_ * C_ * NPB];
__device__ __align__(16) float g_feas[4 * B_ * C_ * NPB];
__device__ float g_fsum[B_ * C_];
__device__ float g_att[B_ * 4 * C_];

// ---------------- angle offset tables ----------------
#define S2  1.4142135623730951
#define S2H 0.7071067811865476
__constant__ float c_ox[45] = {
    0.f,0.f,0.f,0.f,0.f,0.f,0.f,0.f,0.f,
    (float)(1.0-S2), (float)(1.0-S2H), 1.f, (float)(-S2H), 0.f, (float)(S2H),
    -1.f, (float)(S2H-1.0), (float)(S2-1.0),
    0.f,1.f,2.f,-1.f,0.f,1.f,-2.f,-1.f,0.f,
    1.f, (float)(1.0+S2H), (float)(1.0+S2), (float)(-S2H), 0.f, (float)(S2H),
    (float)(-1.0-S2), (float)(-1.0-S2H), -1.f,
    2.f,2.f,2.f,0.f,0.f,0.f,-2.f,-2.f,-2.f
};
__constant__ float c_oy[45] = {
    0.f,0.f,0.f,0.f,0.f,0.f,0.f,0.f,0.f,
    1.f, (float)(S2H), (float)(S2-1.0), (float)(1.0-S2H), 0.f, (float)(S2H-1.0),
    (float)(1.0-S2), (float)(-S2H), -1.f,
    2.f,1.f,0.f,1.f,0.f,-1.f,0.f,-1.f,-2.f,
    (float)(1.0+S2), (float)(S2H), -1.f, (float)(1.0+S2H), 0.f, (float)(-1.0-S2H),
    1.f, (float)(-S2H), (float)(1.0+S2),
    2.f,0.f,-2.f,2.f,0.f,-2.f,2.f,0.f,-2.f
};

// ---------------- helpers ----------------
__device__ __forceinline__ uint32_t smem_u32(const void* p) {
    uint32_t a;
    asm("{ .reg .u64 t; cvta.to.shared.u64 t, %1; cvt.u32.u64 %0, t; }" : "=r"(a) : "l"(p));
    return a;
}
__device__ __forceinline__ void sts128(uint32_t a, uint32_t r0, uint32_t r1, uint32_t r2, uint32_t r3) {
    asm volatile("st.shared.v4.b32 [%0], {%1,%2,%3,%4};" :: "r"(a), "r"(r0), "r"(r1), "r"(r2), "r"(r3) : "memory");
}
__device__ __forceinline__ void ldmx4(uint32_t* r, uint32_t addr) {
    asm volatile("ldmatrix.sync.aligned.m8n8.x4.shared.b16 {%0,%1,%2,%3}, [%4];"
                 : "=r"(r[0]), "=r"(r[1]), "=r"(r[2]), "=r"(r[3]) : "r"(addr));
}
__device__ __forceinline__ void mma_bf16(float4& d, const uint32_t a[4], uint32_t b0, uint32_t b1) {
    asm volatile("mma.sync.aligned.m16n8k16.row.col.f32.bf16.bf16.f32 "
                 "{%0,%1,%2,%3}, {%4,%5,%6,%7}, {%8,%9}, {%0,%1,%2,%3};"
                 : "+f"(d.x), "+f"(d.y), "+f"(d.z), "+f"(d.w)
                 : "r"(a[0]), "r"(a[1]), "r"(a[2]), "r"(a[3]), "r"(b0), "r"(b1));
}
__device__ __forceinline__ unsigned pack_hl(float x) {
    __nv_bfloat16 h = __float2bfloat16(x);
    float r = x - __bfloat162float(h);
    __nv_bfloat16 l = __float2bfloat16(r);
    return (unsigned)__bfloat16_as_ushort(h) | ((unsigned)__bfloat16_as_ushort(l) << 16);
}

// ---------------- 0) prep: k-offset table + packed weights ----------------
__global__ void prep_kernel(const float* __restrict__ w) {
    int i = blockIdx.x * blockDim.x + threadIdx.x;
    if (i < KK) {
        int ci = i / 9, r9 = i - ci * 9;
        g_koff[i] = ci * PLANE3 + (r9 / 3) * H3 + (r9 % 3);
    }
    if (i < C_ * KK) g_wP[i] = pack_hl(w[i]);
}

// ---------------- 1) bilinear resample (packed hi/lo output) ----------------
__global__ void sample_kernel(const float* __restrict__ x) {
    int idx = blockIdx.x * blockDim.x + threadIdx.x;
    const int total = NA * B_ * C_ * PLANE3;
    if (idx >= total) return;

    int cc = idx % H3;  int t = idx / H3;
    int r  = t % H3;    t /= H3;
    int c  = t % C_;    t /= C_;
    int bb = t % B_;    int a = t / B_;

    int i = r / 3, ki = r % 3;
    int j = cc / 3, kj = cc % 3;
    int k = ki * 3 + kj;

    float sx = (float)(ki - 1) + c_ox[a * 9 + k];
    float sy = (float)(kj - 1) + c_oy[a * 9 + k];
    float px = (float)(i + 1) + sx;
    float py = (float)(j + 1) + sy;

    float fx = floorf(px), fy = floorf(py);
    const float HI = 49.f;
    float ltx = fminf(fmaxf(fx,       0.f), HI);
    float lty = fminf(fmaxf(fy,       0.f), HI);
    float rbx = fminf(fmaxf(fx + 1.f, 0.f), HI);
    float rby = fminf(fmaxf(fy + 1.f, 0.f), HI);
    float pxc = fminf(fmaxf(px,       0.f), HI);
    float pyc = fminf(fmaxf(py,       0.f), HI);

    float g_lt = (1.f + (ltx - pxc)) * (1.f + (lty - pyc));
    float g_rb = (1.f - (rbx - pxc)) * (1.f - (rby - pyc));
    float g_lb = (1.f + (ltx - pxc)) * (1.f - (rby - pyc));
    float g_rt = (1.f - (rbx - pxc)) * (1.f + (lty - pyc));

    int ix0 = (int)ltx, iy0 = (int)lty, ix1 = (int)rbx, iy1 = (int)rby;

    const float* xp = x + (bb * C_ + c) * (Hh * Ww);
    auto gat = [&](int ix, int iy) -> float {
        ix -= 1; iy -= 1;
        if (ix < 0 || ix >= Hh || iy < 0 || iy >= Ww) return 0.f;
        return xp[ix * Ww + iy];
    };

    float v = g_lt * gat(ix0, iy0) + g_rb * gat(ix1, iy1)
            + g_lb * gat(ix0, iy1) + g_rt * gat(ix1, iy0);

    g_xoP[((a * B_ + bb) * C_ + c) * PLANE3 + r * H3 + cc] = pack_hl(v);
}

// ---------------- 2) mma.sync implicit-GEMM conv + fused BN/ReLU ----------------
__global__ void __launch_bounds__(256)
conv_mma_kernel(const float* __restrict__ gma, const float* __restrict__ bta,
                const float* __restrict__ mu,  const float* __restrict__ var) {
    extern __shared__ char smem[];
    const uint32_t sb = smem_u32(smem);
    const int tid = threadIdx.x;
    const int a = blockIdx.z;
    const int coBase = blockIdx.y * TILE_M;
    const int nBase  = blockIdx.x * TILE_N;
    const int lane = tid & 31, wid = tid >> 5;
    const int wm = wid & 3, wn = wid >> 2;   // warp tile: m 32 @ wm*32, n 64 @ wn*64

    // ---- fill mappings: thread -> (row fm, kstep fks) ----
    const int fm  = tid & 127;
    const int fks = tid >> 7;
    const unsigned* wrowp = g_wP + (coBase + fm) * KK + fks * 16;
    const int* koffp = g_koff + fks * 16;
    const int nG = nBase + fm;
    const bool okB = nG < NTOT;
    int preOff = 0;
    if (okB) {
        int bb = nG / NPB;
        int p  = nG - bb * NPB;
        int u  = p / WO, v = p - u * WO;
        preOff = ((a * B_ + bb) * C_) * PLANE3 + u * H3 + v;
    }
    const uint32_t aFill = sb + OFF_AH + (uint32_t)fks * KSTEPB + (uint32_t)fm * ROWB;
    const uint32_t bFill = sb + OFF_BH + (uint32_t)fks * KSTEPB + (uint32_t)fm * ROWB;

    float4 acc[2][8];
#pragma unroll
    for (int i = 0; i < 2; i++)
#pragma unroll
        for (int j = 0; j < 8; j++) acc[i][j] = make_float4(0.f, 0.f, 0.f, 0.f);

    // ---- ldmatrix addresses (per thread constants) ----
    const uint32_t aLd = (uint32_t)(wm * 32 + (lane & 15)) * ROWB + (uint32_t)(lane >> 4) * 16;
    const uint32_t bLd = (uint32_t)(wn * 64 + ((lane >> 4) << 3) + (lane & 7)) * ROWB
                       + (uint32_t)((lane >> 3) & 1) * 16;

    unsigned qa[16], qb[16];

    auto loadChunk = [&](int kt) {
        const unsigned* wp = wrowp + kt;
        *(uint4*)&qa[0]  = *(const uint4*)(wp);
        *(uint4*)&qa[4]  = *(const uint4*)(wp + 4);
        *(uint4*)&qa[8]  = *(const uint4*)(wp + 8);
        *(uint4*)&qa[12] = *(const uint4*)(wp + 12);
#pragma unroll
        for (int j = 0; j < 16; j++)
            qb[j] = okB ? g_xoP[koffp[kt + j] + preOff] : 0u;
    };
    auto stsChunk = [&](uint32_t stageOff) {
        uint32_t h[8], l[8];
#pragma unroll
        for (int j = 0; j < 8; j++) {
            h[j] = (qa[2*j] & 0xFFFFu) | (qa[2*j+1] << 16);
            l[j] = (qa[2*j] >> 16) | (qa[2*j+1] & 0xFFFF0000u);
        }
        sts128(aFill + stageOff,      h[0], h[1], h[2], h[3]);
        sts128(aFill + stageOff + 16, h[4], h[5], h[6], h[7]);
        sts128(aFill + stageOff + (OFF_AL - OFF_AH),      l[0], l[1], l[2], l[3]);
        sts128(aFill + stageOff + (OFF_AL - OFF_AH) + 16, l[4], l[5], l[6], l[7]);
#pragma unroll
        for (int j = 0; j < 8; j++) {
            h[j] = (qb[2*j] & 0xFFFFu) | (qb[2*j+1] << 16);
            l[j] = (qb[2*j] >> 16) | (qb[2*j+1] & 0xFFFF0000u);
        }
        sts128(bFill + stageOff,      h[0], h[1], h[2], h[3]);
        sts128(bFill + stageOff + 16, h[4], h[5], h[6], h[7]);
        sts128(bFill + stageOff + (OFF_BL - OFF_BH),      l[0], l[1], l[2], l[3]);
        sts128(bFill + stageOff + (OFF_BL - OFF_BH) + 16, l[4], l[5], l[6], l[7]);
    };
    auto computeStage = [&](uint32_t stageOff) {
#pragma unroll
        for (int ks = 0; ks < 2; ks++) {
            const uint32_t base = sb + stageOff + (uint32_t)ks * KSTEPB;
            uint32_t aH[2][4], aL[2][4], bH[4][4], bL[4][4];
#pragma unroll
            for (int mt = 0; mt < 2; mt++) {
                uint32_t ad = base + OFF_AH + aLd + (uint32_t)(mt * 16) * ROWB;
                ldmx4(aH[mt], ad);
                ldmx4(aL[mt], ad + (OFF_AL - OFF_AH));
            }
#pragma unroll
            for (int bt = 0; bt < 4; bt++) {
                uint32_t bd = base + OFF_BH + bLd + (uint32_t)(bt * 16) * ROWB;
                ldmx4(bH[bt], bd);
                ldmx4(bL[bt], bd + (OFF_BL - OFF_BH));
            }
#pragma unroll
            for (int mt = 0; mt < 2; mt++)
#pragma unroll
                for (int nt = 0; nt < 8; nt++) {
                    uint32_t b0h = bH[nt >> 1][(nt & 1) * 2], b1h = bH[nt >> 1][(nt & 1) * 2 + 1];
                    uint32_t b0l = bL[nt >> 1][(nt & 1) * 2], b1l = bL[nt >> 1][(nt & 1) * 2 + 1];
                    mma_bf16(acc[mt][nt], aH[mt], b0h, b1h);
                    mma_bf16(acc[mt][nt], aH[mt], b0l, b1l);
                    mma_bf16(acc[mt][nt], aL[mt], b0h, b1h);
                }
        }
    };

    // ---- software-pipelined main loop ----
    loadChunk(0);
    stsChunk(0);
    __syncthreads();
    for (int ch = 0; ch < NCHUNK; ch++) {
        const bool more = (ch + 1) < NCHUNK;
        if (more) loadChunk((ch + 1) * CHUNK);
        computeStage((uint32_t)(ch & 1) * STAGE);
        if (more) {
            __syncthreads();
            stsChunk((uint32_t)((ch + 1) & 1) * STAGE);
            __syncthreads();
        }
    }

    // ---- epilogue: BN+ReLU fused, direct register stores ----
    const int r0 = lane >> 2;
    const int cq = (lane & 3) * 2;
    auto storeV = [&](int co, int n, float v, float sc, float sh) {
        if (n >= NTOT) return;
        int bb = n / NPB;
        int p  = n - bb * NPB;
        if (a == 0) {
            g_y0[(bb * C_ + co) * NPB + p] = v;
        } else {
            g_feas[(((a - 1) * B_ + bb) * C_ + co) * NPB + p] = fmaxf(fmaf(v, sc, sh), 0.f);
        }
    };
#pragma unroll
    for (int mt = 0; mt < 2; mt++) {
        int co0 = coBase + wm * 32 + mt * 16 + r0;
        int co1 = co0 + 8;
        float sc0 = 1.f, sh0 = 0.f, sc1 = 1.f, sh1 = 0.f;
        if (a > 0) {
            int br = a - 1;
            float v0 = var[br * C_ + co0], v1 = var[br * C_ + co1];
            sc0 = gma[br * C_ + co0] * rsqrtf(v0 + 1e-5f);
            sc1 = gma[br * C_ + co1] * rsqrtf(v1 + 1e-5f);
            sh0 = bta[br * C_ + co0] - mu[br * C_ + co0] * sc0;
            sh1 = bta[br * C_ + co1] - mu[br * C_ + co1] * sc1;
        }
#pragma unroll
        for (int nt = 0; nt < 8; nt++) {
            int n0 = nBase + wn * 64 + nt * 8 + cq;
            float4 d = acc[mt][nt];
            storeV(co0, n0,     d.x, sc0, sh0);
            storeV(co0, n0 + 1, d.y, sc0, sh0);
            storeV(co1, n0,     d.z, sc1, sh1);
            storeV(co1, n0 + 1, d.w, sc1, sh1);
        }
    }
}

// ---------------- 3) per-(b,c) sum of feas ----------------
__global__ void reduce_kernel() {
    int bc = blockIdx.x;
    float s = 0.f;
    for (int m = 0; m < 4; m++) {
        const float4* p = (const float4*)&g_feas[(m * B_ * C_ + bc) * NPB];
        for (int i = threadIdx.x; i < NQ; i += 256) {
            float4 v = p[i];
            s += (v.x + v.y) + (v.z + v.w);
        }
    }
    __shared__ float sm[256];
    sm[threadIdx.x] = s;
    __syncthreads();
    for (int st = 128; st > 0; st >>= 1) {
        if (threadIdx.x < st) sm[threadIdx.x] += sm[threadIdx.x + st];
        __syncthreads();
    }
    if (threadIdx.x == 0) g_fsum[bc] = sm[0];
}

// ---------------- 4) attention ----------------
__global__ void att_kernel(const float* __restrict__ fc1w, const float* __restrict__ fc1b,
                           const float* __restrict__ fc2w, const float* __restrict__ fc2b) {
    __shared__ float s_fs[B_ * C_];
    __shared__ float s_z[B_ * 32];
    __shared__ float s_att[B_ * 4 * C_];
    int t = threadIdx.x;

    for (int i = t; i < B_ * C_; i += 256)
        s_fs[i] = g_fsum[i] * (1.f / (float)NPB);
    __syncthreads();

    {   // fea_z: 64 (b,d) pairs x 4 lanes each
        int pair = t >> 2;
        int b = pair >> 5, d = pair & 31;
        int sl = t & 3;
        float s = 0.f;
        for (int c = sl; c < C_; c += 4) s += s_fs[b * C_ + c] * fc1w[d * C_ + c];
        s += __shfl_down_sync(0xffffffffu, s, 2, 4);
        s += __shfl_down_sync(0xffffffffu, s, 1, 4);
        if (sl == 0) s_z[b * 32 + d] = s + fc1b[d];
    }
    __syncthreads();

    for (int i = t; i < B_ * 4 * C_; i += 256) {
        int c = i % C_; int bm = i / C_; int m = bm % 4; int b = bm / 4;
        float s = fc2b[m * C_ + c];
        const float* wr = fc2w + (m * C_ + c) * 32;
#pragma unroll
        for (int d = 0; d < 32; d++) s += s_z[b * 32 + d] * wr[d];
        s_att[(b * 4 + m) * C_ + c] = s;
    }
    __syncthreads();

    for (int i = t; i < B_ * C_; i += 256) {
        int b = i / C_, c = i % C_;
        float a0 = s_att[(b * 4 + 0) * C_ + c];
        float a1 = s_att[(b * 4 + 1) * C_ + c];
        float a2 = s_att[(b * 4 + 2) * C_ + c];
        float a3 = s_att[(b * 4 + 3) * C_ + c];
        float mx = fmaxf(fmaxf(a0, a1), fmaxf(a2, a3));
        float e0 = expf(a0 - mx), e1 = expf(a1 - mx), e2 = expf(a2 - mx), e3 = expf(a3 - mx);
        float inv = 1.f / (e0 + e1 + e2 + e3);
        g_att[(b * 4 + 0) * C_ + c] = e0 * inv;
        g_att[(b * 4 + 1) * C_ + c] = e1 * inv;
        g_att[(b * 4 + 2) * C_ + c] = e2 * inv;
        g_att[(b * 4 + 3) * C_ + c] = e3 * inv;
    }
}

// ---------------- 5) final blend ----------------
__global__ void final_kernel(float* __restrict__ out) {
    int idx = blockIdx.x * blockDim.x + threadIdx.x;
    const int total = B_ * C_ * NQ;
    if (idx >= total) return;
    int pq = idx % NQ;
    int bc = idx / NQ;
    int c  = bc % C_, b = bc / C_;

    float4 o = ((const float4*)&g_y0[bc * NPB])[pq];
#pragma unroll
    for (int m = 0; m < 4; m++) {
        float wm = g_att[(b * 4 + m) * C_ + c];
        float4 f = ((const float4*)&g_feas[(m * B_ * C_ + bc) * NPB])[pq];
        o.x = fmaf(f.x, wm, o.x);
        o.y = fmaf(f.y, wm, o.y);
        o.z = fmaf(f.z, wm, o.z);
        o.w = fmaf(f.w, wm, o.w);
    }
    ((float4*)out)[idx] = o;
}

// ---------------- launch ----------------
extern "C" void kernel_launch(void* const* d_in, const int* in_sizes, int n_in,
                              void* d_out, int out_size) {
    const float* x    = (const float*)d_in[0];
    const float* w    = (const float*)d_in[1];
    const float* gma  = (const float*)d_in[2];
    const float* bta  = (const float*)d_in[3];
    const float* mu   = (const float*)d_in[4];
    const float* var  = (const float*)d_in[5];
    const float* fc1w = (const float*)d_in[6];
    const float* fc1b = (const float*)d_in[7];
    const float* fc2w = (const float*)d_in[8];
    const float* fc2b = (const float*)d_in[9];
    float* out = (float*)d_out;

    cudaFuncSetAttribute(conv_mma_kernel,
                         cudaFuncAttributeMaxDynamicSharedMemorySize, SMEM_TOTAL);

    prep_kernel<<<(C_ * KK + 255) / 256, 256>>>(w);

    const int totS = NA * B_ * C_ * PLANE3;
    sample_kernel<<<(totS + 255) / 256, 256>>>(x);

    dim3 grid(NTILES, C_ / TILE_M, NA);
    conv_mma_kernel<<<grid, 256, SMEM_TOTAL>>>(gma, bta, mu, var);

    reduce_kernel<<<B_ * C_, 256>>>();
    att_kernel<<<1, 256>>>(fc1w, fc1b, fc2w, fc2b);
    final_kernel<<<(B_ * C_ * NQ + 255) / 256, 256>>>(out);
}

// round 5
// speedup vs baseline: 2.1286x; 1.0831x over previous
#include <cuda_runtime.h>
#include <cuda_fp16.h>
#include <cstdint>

// ---------------- problem constants ----------------
constexpr int B_   = 2;
constexpr int C_   = 256;
constexpr int Hh   = 48;
constexpr int Ww   = 48;
constexpr int H3   = 144;            // 3*48 sampled grid
constexpr int HO   = 142, WO = 142;  // VALID 3x3 conv output
constexpr int NPB  = HO * WO;        // 20164
constexpr int NTOT = B_ * NPB;       // 40328
constexpr int KK   = C_ * 9;         // 2304
constexpr int PLANE3 = H3 * H3;      // 20736
constexpr int NA   = 5;              // angles
constexpr int NQ   = NPB / 4;        // 5041

// conv-GEMM tiling (mma.sync fp16 path)
constexpr int TILE_M = 128;
constexpr int TILE_N = 128;
constexpr int CHUNK  = 32;                  // k per chunk (2 ksteps of 16)
constexpr int NCHUNK = KK / CHUNK;          // 72
constexpr int NTILES = (NTOT + TILE_N - 1) / TILE_N;   // 316

// smem: per stage, 3 operand planes (A hi, A lo, B), each 2 ksteps x 128 rows x 48B
constexpr int ROWB   = 48;                  // 32B payload + 16B pad (ldmatrix conflict-free)
constexpr int KSTEPB = 128 * ROWB;          // 6144
constexpr int OFF_AH = 0;
constexpr int OFF_AL = 2 * KSTEPB;          // 12288
constexpr int OFF_B  = 4 * KSTEPB;          // 24576
constexpr int STAGE  = 6 * KSTEPB;          // 36864
constexpr int SMEM_TOTAL = 2 * STAGE;       // 73728

// ---------------- static scratch ----------------
__device__ __align__(16) unsigned short g_xoH[NA * B_ * C_ * PLANE3];  // fp16 sampled data
__device__ __align__(16) unsigned g_wP[C_ * KK];                       // packed fp16 hi|lo<<16 weights
__device__ int   g_koff[KK];
__device__ __align__(16) float g_y0[B_ * C_ * NPB];
__device__ __align__(16) float g_feas[4 * B_ * C_ * NPB];
__device__ float g_fsum[B_ * C_];
__device__ float g_att[B_ * 4 * C_];

// ---------------- angle offset tables ----------------
#define S2  1.4142135623730951
#define S2H 0.7071067811865476
__constant__ float c_ox[45] = {
    0.f,0.f,0.f,0.f,0.f,0.f,0.f,0.f,0.f,
    (float)(1.0-S2), (float)(1.0-S2H), 1.f, (float)(-S2H), 0.f, (float)(S2H),
    -1.f, (float)(S2H-1.0), (float)(S2-1.0),
    0.f,1.f,2.f,-1.f,0.f,1.f,-2.f,-1.f,0.f,
    1.f, (float)(1.0+S2H), (float)(1.0+S2), (float)(-S2H), 0.f, (float)(S2H),
    (float)(-1.0-S2), (float)(-1.0-S2H), -1.f,
    2.f,2.f,2.f,0.f,0.f,0.f,-2.f,-2.f,-2.f
};
__constant__ float c_oy[45] = {
    0.f,0.f,0.f,0.f,0.f,0.f,0.f,0.f,0.f,
    1.f, (float)(S2H), (float)(S2-1.0), (float)(1.0-S2H), 0.f, (float)(S2H-1.0),
    (float)(1.0-S2), (float)(-S2H), -1.f,
    2.f,1.f,0.f,1.f,0.f,-1.f,0.f,-1.f,-2.f,
    (float)(1.0+S2), (float)(S2H), -1.f, (float)(1.0+S2H), 0.f, (float)(-1.0-S2H),
    1.f, (float)(-S2H), (float)(1.0+S2),
    2.f,0.f,-2.f,2.f,0.f,-2.f,2.f,0.f,-2.f
};

// ---------------- helpers ----------------
__device__ __forceinline__ uint32_t smem_u32(const void* p) {
    uint32_t a;
    asm("{ .reg .u64 t; cvta.to.shared.u64 t, %1; cvt.u32.u64 %0, t; }" : "=r"(a) : "l"(p));
    return a;
}
__device__ __forceinline__ void sts128(uint32_t a, uint32_t r0, uint32_t r1, uint32_t r2, uint32_t r3) {
    asm volatile("st.shared.v4.b32 [%0], {%1,%2,%3,%4};" :: "r"(a), "r"(r0), "r"(r1), "r"(r2), "r"(r3) : "memory");
}
__device__ __forceinline__ void ldmx4(uint32_t* r, uint32_t addr) {
    asm volatile("ldmatrix.sync.aligned.m8n8.x4.shared.b16 {%0,%1,%2,%3}, [%4];"
                 : "=r"(r[0]), "=r"(r[1]), "=r"(r[2]), "=r"(r[3]) : "r"(addr));
}
__device__ __forceinline__ void mma_fp16(float4& d, const uint32_t a[4], uint32_t b0, uint32_t b1) {
    asm volatile("mma.sync.aligned.m16n8k16.row.col.f32.f16.f16.f32 "
                 "{%0,%1,%2,%3}, {%4,%5,%6,%7}, {%8,%9}, {%0,%1,%2,%3};"
                 : "+f"(d.x), "+f"(d.y), "+f"(d.z), "+f"(d.w)
                 : "r"(a[0]), "r"(a[1]), "r"(a[2]), "r"(a[3]), "r"(b0), "r"(b1));
}
__device__ __forceinline__ unsigned pack_hl_f16(float x) {
    __half h = __float2half_rn(x);
    float r = x - __half2float(h);
    __half l = __float2half_rn(r);
    return (unsigned)__half_as_ushort(h) | ((unsigned)__half_as_ushort(l) << 16);
}

// ---------------- 0) prep: k-offset table + packed fp16 weights ----------------
__global__ void prep_kernel(const float* __restrict__ w) {
    int i = blockIdx.x * blockDim.x + threadIdx.x;
    if (i < KK) {
        int ci = i / 9, r9 = i - ci * 9;
        g_koff[i] = ci * PLANE3 + (r9 / 3) * H3 + (r9 % 3);
    }
    if (i < C_ * KK) g_wP[i] = pack_hl_f16(w[i]);
}

// ---------------- 1) bilinear resample (fp16 output) ----------------
__global__ void sample_kernel(const float* __restrict__ x) {
    int idx = blockIdx.x * blockDim.x + threadIdx.x;
    const int total = NA * B_ * C_ * PLANE3;
    if (idx >= total) return;

    int cc = idx % H3;  int t = idx / H3;
    int r  = t % H3;    t /= H3;
    int c  = t % C_;    t /= C_;
    int bb = t % B_;    int a = t / B_;

    int i = r / 3, ki = r % 3;
    int j = cc / 3, kj = cc % 3;
    int k = ki * 3 + kj;

    float sx = (float)(ki - 1) + c_ox[a * 9 + k];
    float sy = (float)(kj - 1) + c_oy[a * 9 + k];
    float px = (float)(i + 1) + sx;
    float py = (float)(j + 1) + sy;

    float fx = floorf(px), fy = floorf(py);
    const float HI = 49.f;
    float ltx = fminf(fmaxf(fx,       0.f), HI);
    float lty = fminf(fmaxf(fy,       0.f), HI);
    float rbx = fminf(fmaxf(fx + 1.f, 0.f), HI);
    float rby = fminf(fmaxf(fy + 1.f, 0.f), HI);
    float pxc = fminf(fmaxf(px,       0.f), HI);
    float pyc = fminf(fmaxf(py,       0.f), HI);

    float g_lt = (1.f + (ltx - pxc)) * (1.f + (lty - pyc));
    float g_rb = (1.f - (rbx - pxc)) * (1.f - (rby - pyc));
    float g_lb = (1.f + (ltx - pxc)) * (1.f - (rby - pyc));
    float g_rt = (1.f - (rbx - pxc)) * (1.f + (lty - pyc));

    int ix0 = (int)ltx, iy0 = (int)lty, ix1 = (int)rbx, iy1 = (int)rby;

    const float* xp = x + (bb * C_ + c) * (Hh * Ww);
    auto gat = [&](int ix, int iy) -> float {
        ix -= 1; iy -= 1;
        if (ix < 0 || ix >= Hh || iy < 0 || iy >= Ww) return 0.f;
        return xp[ix * Ww + iy];
    };

    float v = g_lt * gat(ix0, iy0) + g_rb * gat(ix1, iy1)
            + g_lb * gat(ix0, iy1) + g_rt * gat(ix1, iy0);

    g_xoH[((a * B_ + bb) * C_ + c) * PLANE3 + r * H3 + cc] =
        __half_as_ushort(__float2half_rn(v));
}

// ---------------- 2) mma.sync fp16 2-pass implicit-GEMM conv + fused BN/ReLU ----------------
__global__ void __launch_bounds__(256)
conv_mma_kernel(const float* __restrict__ gma, const float* __restrict__ bta,
                const float* __restrict__ mu,  const float* __restrict__ var) {
    extern __shared__ char smem[];
    const uint32_t sb = smem_u32(smem);
    const int tid = threadIdx.x;
    const int a = blockIdx.z;
    const int coBase = blockIdx.y * TILE_M;
    const int nBase  = blockIdx.x * TILE_N;
    const int lane = tid & 31, wid = tid >> 5;
    const int wm = wid & 3, wn = wid >> 2;   // warp tile: m 32 @ wm*32, n 64 @ wn*64

    // ---- fill mappings: thread -> (row fm, kstep fks) ----
    const int fm  = tid & 127;
    const int fks = tid >> 7;
    const unsigned* wrowp = g_wP + (coBase + fm) * KK + fks * 16;
    const int* koffp = g_koff + fks * 16;
    const int nG = nBase + fm;
    const bool okB = nG < NTOT;
    int preOff = 0;
    if (okB) {
        int bb = nG / NPB;
        int p  = nG - bb * NPB;
        int u  = p / WO, v = p - u * WO;
        preOff = ((a * B_ + bb) * C_) * PLANE3 + u * H3 + v;
    }
    const uint32_t aFill = sb + OFF_AH + (uint32_t)fks * KSTEPB + (uint32_t)fm * ROWB;
    const uint32_t bFill = sb + OFF_B  + (uint32_t)fks * KSTEPB + (uint32_t)fm * ROWB;

    float4 acc[2][8];
#pragma unroll
    for (int i = 0; i < 2; i++)
#pragma unroll
        for (int j = 0; j < 8; j++) acc[i][j] = make_float4(0.f, 0.f, 0.f, 0.f);

    // ---- ldmatrix addresses (per thread constants) ----
    const uint32_t aLd = (uint32_t)(wm * 32 + (lane & 15)) * ROWB + (uint32_t)(lane >> 4) * 16;
    const uint32_t bLd = (uint32_t)(wn * 64 + ((lane >> 4) << 3) + (lane & 7)) * ROWB
                       + (uint32_t)((lane >> 3) & 1) * 16;

    unsigned qa[16];
    unsigned short qb[16];

    auto loadChunk = [&](int kt) {
        const unsigned* wp = wrowp + kt;
        *(uint4*)&qa[0]  = *(const uint4*)(wp);
        *(uint4*)&qa[4]  = *(const uint4*)(wp + 4);
        *(uint4*)&qa[8]  = *(const uint4*)(wp + 8);
        *(uint4*)&qa[12] = *(const uint4*)(wp + 12);
#pragma unroll
        for (int j = 0; j < 16; j++)
            qb[j] = okB ? g_xoH[koffp[kt + j] + preOff] : (unsigned short)0;
    };
    auto stsChunk = [&](uint32_t stageOff) {
        uint32_t h[8], l[8];
#pragma unroll
        for (int j = 0; j < 8; j++) {
            h[j] = (qa[2*j] & 0xFFFFu) | (qa[2*j+1] << 16);
            l[j] = (qa[2*j] >> 16) | (qa[2*j+1] & 0xFFFF0000u);
        }
        sts128(aFill + stageOff,      h[0], h[1], h[2], h[3]);
        sts128(aFill + stageOff + 16, h[4], h[5], h[6], h[7]);
        sts128(aFill + stageOff + (OFF_AL - OFF_AH),      l[0], l[1], l[2], l[3]);
        sts128(aFill + stageOff + (OFF_AL - OFF_AH) + 16, l[4], l[5], l[6], l[7]);
        uint32_t bpk[8];
#pragma unroll
        for (int j = 0; j < 8; j++)
            bpk[j] = (uint32_t)qb[2*j] | ((uint32_t)qb[2*j+1] << 16);
        sts128(bFill + stageOff,      bpk[0], bpk[1], bpk[2], bpk[3]);
        sts128(bFill + stageOff + 16, bpk[4], bpk[5], bpk[6], bpk[7]);
    };
    auto computeStage = [&](uint32_t stageOff) {
#pragma unroll
        for (int ks = 0; ks < 2; ks++) {
            const uint32_t base = sb + stageOff + (uint32_t)ks * KSTEPB;
            uint32_t aH[2][4], aL[2][4], bV[4][4];
#pragma unroll
            for (int mt = 0; mt < 2; mt++) {
                uint32_t ad = base + OFF_AH + aLd + (uint32_t)(mt * 16) * ROWB;
                ldmx4(aH[mt], ad);
                ldmx4(aL[mt], ad + (OFF_AL - OFF_AH));
            }
#pragma unroll
            for (int bt = 0; bt < 4; bt++) {
                uint32_t bd = base + OFF_B + bLd + (uint32_t)(bt * 16) * ROWB;
                ldmx4(bV[bt], bd);
            }
#pragma unroll
            for (int mt = 0; mt < 2; mt++)
#pragma unroll
                for (int nt = 0; nt < 8; nt++) {
                    uint32_t b0 = bV[nt >> 1][(nt & 1) * 2], b1 = bV[nt >> 1][(nt & 1) * 2 + 1];
                    mma_fp16(acc[mt][nt], aH[mt], b0, b1);
                    mma_fp16(acc[mt][nt], aL[mt], b0, b1);
                }
        }
    };

    // ---- software-pipelined main loop ----
    loadChunk(0);
    stsChunk(0);
    __syncthreads();
    for (int ch = 0; ch < NCHUNK; ch++) {
        const bool more = (ch + 1) < NCHUNK;
        if (more) loadChunk((ch + 1) * CHUNK);
        computeStage((uint32_t)(ch & 1) * STAGE);
        if (more) {
            __syncthreads();
            stsChunk((uint32_t)((ch + 1) & 1) * STAGE);
            __syncthreads();
        }
    }

    // ---- epilogue: BN+ReLU fused, direct register stores ----
    const int r0 = lane >> 2;
    const int cq = (lane & 3) * 2;
    auto storeV = [&](int co, int n, float v, float sc, float sh) {
        if (n >= NTOT) return;
        int bb = n / NPB;
        int p  = n - bb * NPB;
        if (a == 0) {
            g_y0[(bb * C_ + co) * NPB + p] = v;
        } else {
            g_feas[(((a - 1) * B_ + bb) * C_ + co) * NPB + p] = fmaxf(fmaf(v, sc, sh), 0.f);
        }
    };
#pragma unroll
    for (int mt = 0; mt < 2; mt++) {
        int co0 = coBase + wm * 32 + mt * 16 + r0;
        int co1 = co0 + 8;
        float sc0 = 1.f, sh0 = 0.f, sc1 = 1.f, sh1 = 0.f;
        if (a > 0) {
            int br = a - 1;
            float v0 = var[br * C_ + co0], v1 = var[br * C_ + co1];
            sc0 = gma[br * C_ + co0] * rsqrtf(v0 + 1e-5f);
            sc1 = gma[br * C_ + co1] * rsqrtf(v1 + 1e-5f);
            sh0 = bta[br * C_ + co0] - mu[br * C_ + co0] * sc0;
            sh1 = bta[br * C_ + co1] - mu[br * C_ + co1] * sc1;
        }
#pragma unroll
        for (int nt = 0; nt < 8; nt++) {
            int n0 = nBase + wn * 64 + nt * 8 + cq;
            float4 d = acc[mt][nt];
            storeV(co0, n0,     d.x, sc0, sh0);
            storeV(co0, n0 + 1, d.y, sc0, sh0);
            storeV(co1, n0,     d.z, sc1, sh1);
            storeV(co1, n0 + 1, d.w, sc1, sh1);
        }
    }
}

// ---------------- 3) per-(b,c) sum of feas ----------------
__global__ void reduce_kernel() {
    int bc = blockIdx.x;
    float s = 0.f;
    for (int m = 0; m < 4; m++) {
        const float4* p = (const float4*)&g_feas[(m * B_ * C_ + bc) * NPB];
        for (int i = threadIdx.x; i < NQ; i += 256) {
            float4 v = p[i];
            s += (v.x + v.y) + (v.z + v.w);
        }
    }
    __shared__ float sm[256];
    sm[threadIdx.x] = s;
    __syncthreads();
    for (int st = 128; st > 0; st >>= 1) {
        if (threadIdx.x < st) sm[threadIdx.x] += sm[threadIdx.x + st];
        __syncthreads();
    }
    if (threadIdx.x == 0) g_fsum[bc] = sm[0];
}

// ---------------- 4) attention ----------------
__global__ void att_kernel(const float* __restrict__ fc1w, const float* __restrict__ fc1b,
                           const float* __restrict__ fc2w, const float* __restrict__ fc2b) {
    __shared__ float s_fs[B_ * C_];
    __shared__ float s_z[B_ * 32];
    __shared__ float s_att[B_ * 4 * C_];
    int t = threadIdx.x;

    for (int i = t; i < B_ * C_; i += 256)
        s_fs[i] = g_fsum[i] * (1.f / (float)NPB);
    __syncthreads();

    {   // fea_z: 64 (b,d) pairs x 4 lanes each
        int pair = t >> 2;
        int b = pair >> 5, d = pair & 31;
        int sl = t & 3;
        float s = 0.f;
        for (int c = sl; c < C_; c += 4) s += s_fs[b * C_ + c] * fc1w[d * C_ + c];
        s += __shfl_down_sync(0xffffffffu, s, 2, 4);
        s += __shfl_down_sync(0xffffffffu, s, 1, 4);
        if (sl == 0) s_z[b * 32 + d] = s + fc1b[d];
    }
    __syncthreads();

    for (int i = t; i < B_ * 4 * C_; i += 256) {
        int c = i % C_; int bm = i / C_; int m = bm % 4; int b = bm / 4;
        float s = fc2b[m * C_ + c];
        const float* wr = fc2w + (m * C_ + c) * 32;
#pragma unroll
        for (int d = 0; d < 32; d++) s += s_z[b * 32 + d] * wr[d];
        s_att[(b * 4 + m) * C_ + c] = s;
    }
    __syncthreads();

    for (int i = t; i < B_ * C_; i += 256) {
        int b = i / C_, c = i % C_;
        float a0 = s_att[(b * 4 + 0) * C_ + c];
        float a1 = s_att[(b * 4 + 1) * C_ + c];
        float a2 = s_att[(b * 4 + 2) * C_ + c];
        float a3 = s_att[(b * 4 + 3) * C_ + c];
        float mx = fmaxf(fmaxf(a0, a1), fmaxf(a2, a3));
        float e0 = expf(a0 - mx), e1 = expf(a1 - mx), e2 = expf(a2 - mx), e3 = expf(a3 - mx);
        float inv = 1.f / (e0 + e1 + e2 + e3);
        g_att[(b * 4 + 0) * C_ + c] = e0 * inv;
        g_att[(b * 4 + 1) * C_ + c] = e1 * inv;
        g_att[(b * 4 + 2) * C_ + c] = e2 * inv;
        g_att[(b * 4 + 3) * C_ + c] = e3 * inv;
    }
}

// ---------------- 5) final blend ----------------
__global__ void final_kernel(float* __restrict__ out) {
    int idx = blockIdx.x * blockDim.x + threadIdx.x;
    const int total = B_ * C_ * NQ;
    if (idx >= total) return;
    int pq = idx % NQ;
    int bc = idx / NQ;
    int c  = bc % C_, b = bc / C_;

    float4 o = ((const float4*)&g_y0[bc * NPB])[pq];
#pragma unroll
    for (int m = 0; m < 4; m++) {
        float wm = g_att[(b * 4 + m) * C_ + c];
        float4 f = ((const float4*)&g_feas[(m * B_ * C_ + bc) * NPB])[pq];
        o.x = fmaf(f.x, wm, o.x);
        o.y = fmaf(f.y, wm, o.y);
        o.z = fmaf(f.z, wm, o.z);
        o.w = fmaf(f.w, wm, o.w);
    }
    ((float4*)out)[idx] = o;
}

// ---------------- launch ----------------
extern "C" void kernel_launch(void* const* d_in, const int* in_sizes, int n_in,
                              void* d_out, int out_size) {
    const float* x    = (const float*)d_in[0];
    const float* w    = (const float*)d_in[1];
    const float* gma  = (const float*)d_in[2];
    const float* bta  = (const float*)d_in[3];
    const float* mu   = (const float*)d_in[4];
    const float* var  = (const float*)d_in[5];
    const float* fc1w = (const float*)d_in[6];
    const float* fc1b = (const float*)d_in[7];
    const float* fc2w = (const float*)d_in[8];
    const float* fc2b = (const float*)d_in[9];
    float* out = (float*)d_out;

    cudaFuncSetAttribute(conv_mma_kernel,
                         cudaFuncAttributeMaxDynamicSharedMemorySize, SMEM_TOTAL);

    prep_kernel<<<(C_ * KK + 255) / 256, 256>>>(w);

    const int totS = NA * B_ * C_ * PLANE3;
    sample_kernel<<<(totS + 255) / 256, 256>>>(x);

    dim3 grid(NTILES, C_ / TILE_M, NA);
    conv_mma_kernel<<<grid, 256, SMEM_TOTAL>>>(gma, bta, mu, var);

    reduce_kernel<<<B_ * C_, 256>>>();
    att_kernel<<<1, 256>>>(fc1w, fc1b, fc2w, fc2b);
    final_kernel<<<(B_ * C_ * NQ + 255) / 256, 256>>>(out);
}

// round 6
// speedup vs baseline: 5.1699x; 2.4288x over previous
#include <cuda_runtime.h>
#include <cuda_fp16.h>
#include <cstdint>

// ---------------- problem constants ----------------
constexpr int B_   = 2;
constexpr int C_   = 256;
constexpr int Hh   = 48;
constexpr int Ww   = 48;
constexpr int H3   = 144;            // 3*48 sampled grid
constexpr int HO   = 142, WO = 142;  // VALID 3x3 conv output
constexpr int NPB  = HO * WO;        // 20164
constexpr int NTOT = B_ * NPB;       // 40328
constexpr int KK   = C_ * 9;         // 2304
constexpr int PLANE3 = H3 * H3;      // 20736
constexpr int NA   = 5;              // angles
constexpr int NQ   = NPB / 4;        // 5041
constexpr int TOTXO = NA * B_ * C_ * PLANE3;   // 53,084,160
constexpr int PADE  = 8192;                    // OOB-read padding

// conv-GEMM tiling: n' = u*144 + v over full-width rows (v in [0,144), discard v>=142)
constexpr int TN_B    = HO * H3;     // 20448 n' per batch
constexpr int TILES_B = 160;         // ceil(20448/128)
constexpr int TILE_M  = 128;
constexpr int TILE_N  = 128;
constexpr int CHUNK   = 32;          // k per chunk (2 ksteps of 16)
constexpr int NCHUNK  = KK / CHUNK;  // 72
constexpr int NS      = 4;           // pipeline stages

// smem per stage: A = 128 rows x 80B (64B payload k0..31 + 16 pad),
//                 B = 32 k-rows x 272B (256B payload n0..127 + 16 pad)
constexpr int AROWB = 80;
constexpr int BROWB = 272;
constexpr int OFF_A = 0;
constexpr int OFF_B = 128 * AROWB;                 // 10240
constexpr int STAGE = OFF_B + 32 * BROWB;          // 18944
constexpr int SMEM_TOTAL = NS * STAGE;             // 75776

// ---------------- static scratch ----------------
__device__ __align__(16) unsigned short g_xo0[TOTXO + PADE];  // fp16 sampled, shift 0
__device__ __align__(16) unsigned short g_xo1[TOTXO + PADE];  // shift 1: g_xo1[i] = V[i+1]
__device__ __align__(16) unsigned short g_xo2[TOTXO + PADE];  // shift 2: g_xo2[i] = V[i+2]
__device__ __align__(16) unsigned short g_wH[C_ * KK];        // fp16 weights
__device__ int  g_koff[KK];
__device__ int  g_kdv[KK];
__device__ __align__(16) float g_y0[B_ * C_ * NPB];
__device__ __align__(16) float g_feas[4 * B_ * C_ * NPB];
__device__ float g_fsum[B_ * C_];
__device__ float g_att[B_ * 4 * C_];

// ---------------- angle offset tables ----------------
#define S2  1.4142135623730951
#define S2H 0.7071067811865476
__constant__ float c_ox[45] = {
    0.f,0.f,0.f,0.f,0.f,0.f,0.f,0.f,0.f,
    (float)(1.0-S2), (float)(1.0-S2H), 1.f, (float)(-S2H), 0.f, (float)(S2H),
    -1.f, (float)(S2H-1.0), (float)(S2-1.0),
    0.f,1.f,2.f,-1.f,0.f,1.f,-2.f,-1.f,0.f,
    1.f, (float)(1.0+S2H), (float)(1.0+S2), (float)(-S2H), 0.f, (float)(S2H),
    (float)(-1.0-S2), (float)(-1.0-S2H), -1.f,
    2.f,2.f,2.f,0.f,0.f,0.f,-2.f,-2.f,-2.f
};
__constant__ float c_oy[45] = {
    0.f,0.f,0.f,0.f,0.f,0.f,0.f,0.f,0.f,
    1.f, (float)(S2H), (float)(S2-1.0), (float)(1.0-S2H), 0.f, (float)(S2H-1.0),
    (float)(1.0-S2), (float)(-S2H), -1.f,
    2.f,1.f,0.f,1.f,0.f,-1.f,0.f,-1.f,-2.f,
    (float)(1.0+S2), (float)(S2H), -1.f, (float)(1.0+S2H), 0.f, (float)(-1.0-S2H),
    1.f, (float)(-S2H), (float)(1.0+S2),
    2.f,0.f,-2.f,2.f,0.f,-2.f,2.f,0.f,-2.f
};

// ---------------- helpers ----------------
__device__ __forceinline__ uint32_t smem_u32(const void* p) {
    uint32_t a;
    asm("{ .reg .u64 t; cvta.to.shared.u64 t, %1; cvt.u32.u64 %0, t; }" : "=r"(a) : "l"(p));
    return a;
}
__device__ __forceinline__ void cpasync16(uint32_t dst, const void* src) {
    asm volatile("cp.async.cg.shared.global [%0], [%1], 16;" :: "r"(dst), "l"(src));
}
__device__ __forceinline__ void cp_commit() {
    asm volatile("cp.async.commit_group;" ::: "memory");
}
__device__ __forceinline__ void cp_wait2() {
    asm volatile("cp.async.wait_group %0;" :: "n"(2) : "memory");
}
__device__ __forceinline__ void ldmx4(uint32_t* r, uint32_t addr) {
    asm volatile("ldmatrix.sync.aligned.m8n8.x4.shared.b16 {%0,%1,%2,%3}, [%4];"
                 : "=r"(r[0]), "=r"(r[1]), "=r"(r[2]), "=r"(r[3]) : "r"(addr));
}
__device__ __forceinline__ void ldmx4t(uint32_t* r, uint32_t addr) {
    asm volatile("ldmatrix.sync.aligned.m8n8.x4.trans.shared.b16 {%0,%1,%2,%3}, [%4];"
                 : "=r"(r[0]), "=r"(r[1]), "=r"(r[2]), "=r"(r[3]) : "r"(addr));
}
__device__ __forceinline__ void mma_fp16(float4& d, const uint32_t a[4], uint32_t b0, uint32_t b1) {
    asm volatile("mma.sync.aligned.m16n8k16.row.col.f32.f16.f16.f32 "
                 "{%0,%1,%2,%3}, {%4,%5,%6,%7}, {%8,%9}, {%0,%1,%2,%3};"
                 : "+f"(d.x), "+f"(d.y), "+f"(d.z), "+f"(d.w)
                 : "r"(a[0]), "r"(a[1]), "r"(a[2]), "r"(a[3]), "r"(b0), "r"(b1));
}

// ---------------- 0) prep: tables + fp16 weights ----------------
__global__ void prep_kernel(const float* __restrict__ w) {
    int i = blockIdx.x * blockDim.x + threadIdx.x;
    if (i < KK) {
        int ci = i / 9, r9 = i - ci * 9;
        g_koff[i] = ci * PLANE3 + (r9 / 3) * H3 + (r9 % 3);
        g_kdv[i]  = r9 % 3;
    }
    if (i < C_ * KK) g_wH[i] = __half_as_ushort(__float2half_rn(w[i]));
}

// ---------------- 1) bilinear resample -> fp16, 3 shifted copies ----------------
__global__ void sample_kernel(const float* __restrict__ x) {
    int idx = blockIdx.x * blockDim.x + threadIdx.x;
    if (idx >= TOTXO) return;

    int cc = idx % H3;  int t = idx / H3;
    int r  = t % H3;    t /= H3;
    int c  = t % C_;    t /= C_;
    int bb = t % B_;    int a = t / B_;

    int i = r / 3, ki = r % 3;
    int j = cc / 3, kj = cc % 3;
    int k = ki * 3 + kj;

    float sx = (float)(ki - 1) + c_ox[a * 9 + k];
    float sy = (float)(kj - 1) + c_oy[a * 9 + k];
    float px = (float)(i + 1) + sx;
    float py = (float)(j + 1) + sy;

    float fx = floorf(px), fy = floorf(py);
    const float HI = 49.f;
    float ltx = fminf(fmaxf(fx,       0.f), HI);
    float lty = fminf(fmaxf(fy,       0.f), HI);
    float rbx = fminf(fmaxf(fx + 1.f, 0.f), HI);
    float rby = fminf(fmaxf(fy + 1.f, 0.f), HI);
    float pxc = fminf(fmaxf(px,       0.f), HI);
    float pyc = fminf(fmaxf(py,       0.f), HI);

    float g_lt = (1.f + (ltx - pxc)) * (1.f + (lty - pyc));
    float g_rb = (1.f - (rbx - pxc)) * (1.f - (rby - pyc));
    float g_lb = (1.f + (ltx - pxc)) * (1.f - (rby - pyc));
    float g_rt = (1.f - (rbx - pxc)) * (1.f + (lty - pyc));

    int ix0 = (int)ltx, iy0 = (int)lty, ix1 = (int)rbx, iy1 = (int)rby;

    const float* xp = x + (bb * C_ + c) * (Hh * Ww);
    auto gat = [&](int ix, int iy) -> float {
        ix -= 1; iy -= 1;
        if (ix < 0 || ix >= Hh || iy < 0 || iy >= Ww) return 0.f;
        return xp[ix * Ww + iy];
    };

    float v = g_lt * gat(ix0, iy0) + g_rb * gat(ix1, iy1)
            + g_lb * gat(ix0, iy1) + g_rt * gat(ix1, iy0);

    unsigned short h = __half_as_ushort(__float2half_rn(v));
    g_xo0[idx] = h;
    if (idx >= 1) g_xo1[idx - 1] = h;
    if (idx >= 2) g_xo2[idx - 2] = h;
}

// ---------------- 2) mma.sync fp16 1-pass implicit-GEMM conv + fused BN/ReLU ----------------
__global__ void __launch_bounds__(256)
conv_mma_kernel(const float* __restrict__ gma, const float* __restrict__ bta,
                const float* __restrict__ mu,  const float* __restrict__ var) {
    extern __shared__ char smem[];
    const uint32_t sb = smem_u32(smem);
    const int tid = threadIdx.x;
    const int a  = blockIdx.z;
    const int coBase = blockIdx.y * TILE_M;
    const int bb  = blockIdx.x / TILES_B;
    const int tIn = blockIdx.x - bb * TILES_B;
    const int nOff = tIn * TILE_N;               // n' base within batch
    const int origB = ((a * B_ + bb) * C_) * PLANE3;
    const int lane = tid & 31, wid = tid >> 5;
    const int wm = wid & 3, wn = wid >> 2;       // warp tile: m 32 @ wm*32, n 64 @ wn*64

    // issue-task constants
    const int aRow = tid >> 2, aPc = tid & 3;          // A: rows aRow, aRow+64
    const int bRow = tid >> 4, bPc = tid & 15;         // B: rows bRow, bRow+16

    auto issueChunk = [&](int ch, int st) {
        const uint32_t sg = sb + (uint32_t)st * STAGE;
        // A: 128 rows x 64B, 16B pieces
#pragma unroll
        for (int t2 = 0; t2 < 2; t2++) {
            int row = aRow + t2 * 64;
            const char* src = (const char*)g_wH
                + ((size_t)(coBase + row) * KK + (size_t)ch * CHUNK) * 2 + aPc * 16;
            cpasync16(sg + OFF_A + row * AROWB + aPc * 16, src);
        }
        // B: 32 k-rows x 256B (128 consecutive n'), 16B pieces from shifted copies
#pragma unroll
        for (int t2 = 0; t2 < 2; t2++) {
            int row = bRow + t2 * 16;
            int k = ch * CHUNK + row;
            int ko = g_koff[k];
            int dv = g_kdv[k];
            const unsigned short* bp = (dv == 0) ? g_xo0 : (dv == 1) ? g_xo1 : g_xo2;
            const char* src = (const char*)bp
                + (size_t)(origB + ko + nOff - dv) * 2 + bPc * 16;
            cpasync16(sg + OFF_B + row * BROWB + bPc * 16, src);
        }
    };

    float4 acc[2][8];
#pragma unroll
    for (int i = 0; i < 2; i++)
#pragma unroll
        for (int j = 0; j < 8; j++) acc[i][j] = make_float4(0.f, 0.f, 0.f, 0.f);

    // ldmatrix per-thread address bases
    const uint32_t aLd = (uint32_t)(wm * 32 + (lane & 15)) * AROWB + (uint32_t)(lane >> 4) * 16;
    const uint32_t bLd0 = (uint32_t)(lane & 15) * BROWB
                        + (uint32_t)(wn * 64 + (lane >> 4) * 8) * 2;

    auto computeStage = [&](int st) {
        const uint32_t sg = sb + (uint32_t)st * STAGE;
#pragma unroll
        for (int ks = 0; ks < 2; ks++) {
            uint32_t aH[2][4], bV[4][4];
#pragma unroll
            for (int mt = 0; mt < 2; mt++)
                ldmx4(aH[mt], sg + OFF_A + aLd + (uint32_t)(mt * 16) * AROWB + ks * 32);
#pragma unroll
            for (int bt = 0; bt < 4; bt++)
                ldmx4t(bV[bt], sg + OFF_B + bLd0 + (uint32_t)(ks * 16) * BROWB + (uint32_t)(bt * 16) * 2);
#pragma unroll
            for (int mt = 0; mt < 2; mt++)
#pragma unroll
                for (int nt = 0; nt < 8; nt++) {
                    uint32_t b0 = bV[nt >> 1][(nt & 1) * 2], b1 = bV[nt >> 1][(nt & 1) * 2 + 1];
                    mma_fp16(acc[mt][nt], aH[mt], b0, b1);
                }
        }
    };

    // ---- prologue: fill stages 0..2 ----
#pragma unroll
    for (int s = 0; s < NS - 1; s++) { issueChunk(s, s); cp_commit(); }

    // ---- main loop: 1 barrier per chunk ----
    for (int ch = 0; ch < NCHUNK; ch++) {
        cp_wait2();                       // stage ch%NS ready
        __syncthreads();                  // visibility + stage-reuse safety
        if (ch + NS - 1 < NCHUNK) issueChunk(ch + NS - 1, (ch + NS - 1) & (NS - 1));
        cp_commit();
        computeStage(ch & (NS - 1));
    }

    // ---- epilogue: BN+ReLU fused, discard v>=142 / n'>=TN_B ----
    const int r0 = lane >> 2;
    const int cq = (lane & 3) * 2;
    auto storeV = [&](int co, int np, float v, float sc, float sh) {
        if (np >= TN_B) return;
        int u = np / H3, vv = np - u * H3;
        if (vv >= WO) return;
        int p = u * WO + vv;
        if (a == 0) {
            g_y0[(bb * C_ + co) * NPB + p] = v;
        } else {
            g_feas[(((a - 1) * B_ + bb) * C_ + co) * NPB + p] = fmaxf(fmaf(v, sc, sh), 0.f);
        }
    };
#pragma unroll
    for (int mt = 0; mt < 2; mt++) {
        int co0 = coBase + wm * 32 + mt * 16 + r0;
        int co1 = co0 + 8;
        float sc0 = 1.f, sh0 = 0.f, sc1 = 1.f, sh1 = 0.f;
        if (a > 0) {
            int br = a - 1;
            float v0 = var[br * C_ + co0], v1 = var[br * C_ + co1];
            sc0 = gma[br * C_ + co0] * rsqrtf(v0 + 1e-5f);
            sc1 = gma[br * C_ + co1] * rsqrtf(v1 + 1e-5f);
            sh0 = bta[br * C_ + co0] - mu[br * C_ + co0] * sc0;
            sh1 = bta[br * C_ + co1] - mu[br * C_ + co1] * sc1;
        }
#pragma unroll
        for (int nt = 0; nt < 8; nt++) {
            int n0 = nOff + wn * 64 + nt * 8 + cq;
            float4 d = acc[mt][nt];
            storeV(co0, n0,     d.x, sc0, sh0);
            storeV(co0, n0 + 1, d.y, sc0, sh0);
            storeV(co1, n0,     d.z, sc1, sh1);
            storeV(co1, n0 + 1, d.w, sc1, sh1);
        }
    }
}

// ---------------- 3) per-(b,c) sum of feas ----------------
__global__ void reduce_kernel() {
    int bc = blockIdx.x;
    float s = 0.f;
    for (int m = 0; m < 4; m++) {
        const float4* p = (const float4*)&g_feas[(m * B_ * C_ + bc) * NPB];
        for (int i = threadIdx.x; i < NQ; i += 256) {
            float4 v = p[i];
            s += (v.x + v.y) + (v.z + v.w);
        }
    }
    __shared__ float sm[256];
    sm[threadIdx.x] = s;
    __syncthreads();
    for (int st = 128; st > 0; st >>= 1) {
        if (threadIdx.x < st) sm[threadIdx.x] += sm[threadIdx.x + st];
        __syncthreads();
    }
    if (threadIdx.x == 0) g_fsum[bc] = sm[0];
}

// ---------------- 4) attention (fc1_w staged in smem) ----------------
__global__ void att_kernel(const float* __restrict__ fc1w, const float* __restrict__ fc1b,
                           const float* __restrict__ fc2w, const float* __restrict__ fc2b) {
    __shared__ float s_w1[32 * C_];
    __shared__ float s_fs[B_ * C_];
    __shared__ float s_z[B_ * 32];
    __shared__ float s_att[B_ * 4 * C_];
    int t = threadIdx.x;

    for (int i = t; i < 32 * C_; i += 256) s_w1[i] = fc1w[i];
    for (int i = t; i < B_ * C_; i += 256)
        s_fs[i] = g_fsum[i] * (1.f / (float)NPB);
    __syncthreads();

    {   // fea_z: 64 (b,d) pairs x 4 lanes each, weights from smem
        int pair = t >> 2;
        int b = pair >> 5, d = pair & 31;
        int sl = t & 3;
        float s = 0.f;
        for (int c = sl; c < C_; c += 4) s += s_fs[b * C_ + c] * s_w1[d * C_ + c];
        s += __shfl_down_sync(0xffffffffu, s, 2, 4);
        s += __shfl_down_sync(0xffffffffu, s, 1, 4);
        if (sl == 0) s_z[b * 32 + d] = s + fc1b[d];
    }
    __syncthreads();

    for (int i = t; i < B_ * 4 * C_; i += 256) {
        int c = i % C_; int bm = i / C_; int m = bm % 4; int b = bm / 4;
        float s = fc2b[m * C_ + c];
        const float* wr = fc2w + (m * C_ + c) * 32;
#pragma unroll
        for (int d = 0; d < 32; d++) s += s_z[b * 32 + d] * wr[d];
        s_att[(b * 4 + m) * C_ + c] = s;
    }
    __syncthreads();

    for (int i = t; i < B_ * C_; i += 256) {
        int b = i / C_, c = i % C_;
        float a0 = s_att[(b * 4 + 0) * C_ + c];
        float a1 = s_att[(b * 4 + 1) * C_ + c];
        float a2 = s_att[(b * 4 + 2) * C_ + c];
        float a3 = s_att[(b * 4 + 3) * C_ + c];
        float mx = fmaxf(fmaxf(a0, a1), fmaxf(a2, a3));
        float e0 = expf(a0 - mx), e1 = expf(a1 - mx), e2 = expf(a2 - mx), e3 = expf(a3 - mx);
        float inv = 1.f / (e0 + e1 + e2 + e3);
        g_att[(b * 4 + 0) * C_ + c] = e0 * inv;
        g_att[(b * 4 + 1) * C_ + c] = e1 * inv;
        g_att[(b * 4 + 2) * C_ + c] = e2 * inv;
        g_att[(b * 4 + 3) * C_ + c] = e3 * inv;
    }
}

// ---------------- 5) final blend ----------------
__global__ void final_kernel(float* __restrict__ out) {
    int idx = blockIdx.x * blockDim.x + threadIdx.x;
    const int total = B_ * C_ * NQ;
    if (idx >= total) return;
    int pq = idx % NQ;
    int bc = idx / NQ;
    int c  = bc % C_, b = bc / C_;

    float4 o = ((const float4*)&g_y0[bc * NPB])[pq];
#pragma unroll
    for (int m = 0; m < 4; m++) {
        float wm = g_att[(b * 4 + m) * C_ + c];
        float4 f = ((const float4*)&g_feas[(m * B_ * C_ + bc) * NPB])[pq];
        o.x = fmaf(f.x, wm, o.x);
        o.y = fmaf(f.y, wm, o.y);
        o.z = fmaf(f.z, wm, o.z);
        o.w = fmaf(f.w, wm, o.w);
    }
    ((float4*)out)[idx] = o;
}

// ---------------- launch ----------------
extern "C" void kernel_launch(void* const* d_in, const int* in_sizes, int n_in,
                              void* d_out, int out_size) {
    const float* x    = (const float*)d_in[0];
    const float* w    = (const float*)d_in[1];
    const float* gma  = (const float*)d_in[2];
    const float* bta  = (const float*)d_in[3];
    const float* mu   = (const float*)d_in[4];
    const float* var  = (const float*)d_in[5];
    const float* fc1w = (const float*)d_in[6];
    const float* fc1b = (const float*)d_in[7];
    const float* fc2w = (const float*)d_in[8];
    const float* fc2b = (const float*)d_in[9];
    float* out = (float*)d_out;

    cudaFuncSetAttribute(conv_mma_kernel,
                         cudaFuncAttributeMaxDynamicSharedMemorySize, SMEM_TOTAL);

    prep_kernel<<<(C_ * KK + 255) / 256, 256>>>(w);
    sample_kernel<<<(TOTXO + 255) / 256, 256>>>(x);

    dim3 grid(B_ * TILES_B, C_ / TILE_M, NA);
    conv_mma_kernel<<<grid, 256, SMEM_TOTAL>>>(gma, bta, mu, var);

    reduce_kernel<<<B_ * C_, 256>>>();
    att_kernel<<<1, 256>>>(fc1w, fc1b, fc2w, fc2b);
    final_kernel<<<(B_ * C_ * NQ + 255) / 256, 256>>>(out);
}

// round 7
// speedup vs baseline: 5.4947x; 1.0628x over previous
#include <cuda_runtime.h>
#include <cuda_fp16.h>
#include <cstdint>

// ---------------- problem constants ----------------
constexpr int B_   = 2;
constexpr int C_   = 256;
constexpr int Hh   = 48;
constexpr int Ww   = 48;
constexpr int H3   = 144;            // 3*48 sampled grid
constexpr int HO   = 142, WO = 142;  // VALID 3x3 conv output
constexpr int NPB  = HO * WO;        // 20164
constexpr int KK   = C_ * 9;         // 2304
constexpr int PLANE3 = H3 * H3;      // 20736
constexpr int NA   = 5;              // angles
constexpr int NQ   = NPB / 4;        // 5041
constexpr int TOTXO = NA * B_ * C_ * PLANE3;   // 53,084,160
constexpr int PADE  = 8192;                    // OOB-read padding

// conv-GEMM tiling: n' = u*144 + v over full-width rows (v in [0,144), discard v>=142)
constexpr int TN_B    = HO * H3;     // 20448 n' per batch
constexpr int TILES_B = 160;         // ceil(20448/128)
constexpr int TILE_M  = 128;
constexpr int TILE_N  = 128;
constexpr int CHUNK   = 32;          // k per chunk (2 ksteps of 16)
constexpr int NCHUNK  = KK / CHUNK;  // 72
constexpr int NS      = 4;           // pipeline stages

// smem per stage: A = 128 rows x 80B, B = 32 k-rows x 272B
constexpr int AROWB = 80;
constexpr int BROWB = 272;
constexpr int OFF_A = 0;
constexpr int OFF_B = 128 * AROWB;                 // 10240
constexpr int STAGE = OFF_B + 32 * BROWB;          // 18944
constexpr int SMEM_TOTAL = NS * STAGE;             // 75776

// ---------------- static scratch ----------------
__device__ __align__(16) unsigned short g_xo0[TOTXO + PADE];  // fp16 sampled, shift 0
__device__ __align__(16) unsigned short g_xo1[TOTXO + PADE];  // shift 1: g_xo1[i] = V[i+1]
__device__ __align__(16) unsigned short g_xo2[TOTXO + PADE];  // shift 2: g_xo2[i] = V[i+2]
__device__ __align__(16) unsigned short g_wH[C_ * KK];        // fp16 weights
__device__ int  g_koff[KK];
__device__ int  g_kdv[KK];
__device__ __align__(16) float  g_y0[B_ * C_ * NPB];
__device__ __align__(16) __half g_feasH[4 * B_ * C_ * NPB];   // fp16 BN+ReLU branches
__device__ float g_fsum[B_ * C_];
__device__ float g_att[B_ * 4 * C_];

// ---------------- angle offset tables ----------------
#define S2  1.4142135623730951
#define S2H 0.7071067811865476
__constant__ float c_ox[45] = {
    0.f,0.f,0.f,0.f,0.f,0.f,0.f,0.f,0.f,
    (float)(1.0-S2), (float)(1.0-S2H), 1.f, (float)(-S2H), 0.f, (float)(S2H),
    -1.f, (float)(S2H-1.0), (float)(S2-1.0),
    0.f,1.f,2.f,-1.f,0.f,1.f,-2.f,-1.f,0.f,
    1.f, (float)(1.0+S2H), (float)(1.0+S2), (float)(-S2H), 0.f, (float)(S2H),
    (float)(-1.0-S2), (float)(-1.0-S2H), -1.f,
    2.f,2.f,2.f,0.f,0.f,0.f,-2.f,-2.f,-2.f
};
__constant__ float c_oy[45] = {
    0.f,0.f,0.f,0.f,0.f,0.f,0.f,0.f,0.f,
    1.f, (float)(S2H), (float)(S2-1.0), (float)(1.0-S2H), 0.f, (float)(S2H-1.0),
    (float)(1.0-S2), (float)(-S2H), -1.f,
    2.f,1.f,0.f,1.f,0.f,-1.f,0.f,-1.f,-2.f,
    (float)(1.0+S2), (float)(S2H), -1.f, (float)(1.0+S2H), 0.f, (float)(-1.0-S2H),
    1.f, (float)(-S2H), (float)(1.0+S2),
    2.f,0.f,-2.f,2.f,0.f,-2.f,2.f,0.f,-2.f
};

// ---------------- helpers ----------------
__device__ __forceinline__ uint32_t smem_u32(const void* p) {
    uint32_t a;
    asm("{ .reg .u64 t; cvta.to.shared.u64 t, %1; cvt.u32.u64 %0, t; }" : "=r"(a) : "l"(p));
    return a;
}
__device__ __forceinline__ void cpasync16(uint32_t dst, const void* src) {
    asm volatile("cp.async.cg.shared.global [%0], [%1], 16;" :: "r"(dst), "l"(src));
}
__device__ __forceinline__ void cp_commit() {
    asm volatile("cp.async.commit_group;" ::: "memory");
}
__device__ __forceinline__ void cp_wait2() {
    asm volatile("cp.async.wait_group %0;" :: "n"(2) : "memory");
}
__device__ __forceinline__ void ldmx4(uint32_t* r, uint32_t addr) {
    asm volatile("ldmatrix.sync.aligned.m8n8.x4.shared.b16 {%0,%1,%2,%3}, [%4];"
                 : "=r"(r[0]), "=r"(r[1]), "=r"(r[2]), "=r"(r[3]) : "r"(addr));
}
__device__ __forceinline__ void ldmx4t(uint32_t* r, uint32_t addr) {
    asm volatile("ldmatrix.sync.aligned.m8n8.x4.trans.shared.b16 {%0,%1,%2,%3}, [%4];"
                 : "=r"(r[0]), "=r"(r[1]), "=r"(r[2]), "=r"(r[3]) : "r"(addr));
}
__device__ __forceinline__ void mma_fp16(float4& d, const uint32_t a[4], uint32_t b0, uint32_t b1) {
    asm volatile("mma.sync.aligned.m16n8k16.row.col.f32.f16.f16.f32 "
                 "{%0,%1,%2,%3}, {%4,%5,%6,%7}, {%8,%9}, {%0,%1,%2,%3};"
                 : "+f"(d.x), "+f"(d.y), "+f"(d.z), "+f"(d.w)
                 : "r"(a[0]), "r"(a[1]), "r"(a[2]), "r"(a[3]), "r"(b0), "r"(b1));
}

// ---------------- 0) prep: tables + fp16 weights + fsum zero ----------------
__global__ void prep_kernel(const float* __restrict__ w) {
    int i = blockIdx.x * blockDim.x + threadIdx.x;
    if (i < KK) {
        int ci = i / 9, r9 = i - ci * 9;
        g_koff[i] = ci * PLANE3 + (r9 / 3) * H3 + (r9 % 3);
        g_kdv[i]  = r9 % 3;
    }
    if (i < B_ * C_) g_fsum[i] = 0.f;
    if (i < C_ * KK) g_wH[i] = __half_as_ushort(__float2half_rn(w[i]));
}

// ---------------- 1) bilinear resample -> fp16, 3 shifted copies ----------------
// grid: (81, C_, NA*B_), block 256; 81*256 == PLANE3
__global__ void sample_kernel(const float* __restrict__ x) {
    int ip = blockIdx.x * 256 + threadIdx.x;     // in-plane index < 20736
    int c  = blockIdx.y;
    int ab = blockIdx.z;                          // a*B_ + bb
    int a  = ab >> 1, bb = ab & 1;

    int r  = ip / H3;
    int cc = ip - r * H3;

    int i = r / 3, ki = r - i * 3;
    int j = cc / 3, kj = cc - j * 3;
    int k = ki * 3 + kj;

    float sx = (float)(ki - 1) + c_ox[a * 9 + k];
    float sy = (float)(kj - 1) + c_oy[a * 9 + k];
    float px = (float)(i + 1) + sx;
    float py = (float)(j + 1) + sy;

    float fx = floorf(px), fy = floorf(py);
    const float HI = 49.f;
    float ltx = fminf(fmaxf(fx,       0.f), HI);
    float lty = fminf(fmaxf(fy,       0.f), HI);
    float rbx = fminf(fmaxf(fx + 1.f, 0.f), HI);
    float rby = fminf(fmaxf(fy + 1.f, 0.f), HI);
    float pxc = fminf(fmaxf(px,       0.f), HI);
    float pyc = fminf(fmaxf(py,       0.f), HI);

    float g_lt = (1.f + (ltx - pxc)) * (1.f + (lty - pyc));
    float g_rb = (1.f - (rbx - pxc)) * (1.f - (rby - pyc));
    float g_lb = (1.f + (ltx - pxc)) * (1.f - (rby - pyc));
    float g_rt = (1.f - (rbx - pxc)) * (1.f + (lty - pyc));

    int ix0 = (int)ltx, iy0 = (int)lty, ix1 = (int)rbx, iy1 = (int)rby;

    const float* xp = x + (bb * C_ + c) * (Hh * Ww);
    auto gat = [&](int ix, int iy) -> float {
        ix -= 1; iy -= 1;
        if (ix < 0 || ix >= Hh || iy < 0 || iy >= Ww) return 0.f;
        return xp[ix * Ww + iy];
    };

    float v = g_lt * gat(ix0, iy0) + g_rb * gat(ix1, iy1)
            + g_lb * gat(ix0, iy1) + g_rt * gat(ix1, iy0);

    unsigned short h = __half_as_ushort(__float2half_rn(v));
    int idx = (ab * C_ + c) * PLANE3 + ip;
    g_xo0[idx] = h;
    if (idx >= 1) g_xo1[idx - 1] = h;
    if (idx >= 2) g_xo2[idx - 2] = h;
}

// ---------------- 2) mma.sync fp16 1-pass implicit-GEMM conv + fused BN/ReLU + fused GAP ----------------
__global__ void __launch_bounds__(256)
conv_mma_kernel(const float* __restrict__ gma, const float* __restrict__ bta,
                const float* __restrict__ mu,  const float* __restrict__ var) {
    extern __shared__ char smem[];
    const uint32_t sb = smem_u32(smem);
    const int tid = threadIdx.x;
    const int a  = blockIdx.z;
    const int coBase = blockIdx.y * TILE_M;
    const int bb  = blockIdx.x / TILES_B;
    const int tIn = blockIdx.x - bb * TILES_B;
    const int nOff = tIn * TILE_N;               // n' base within batch
    const int origB = ((a * B_ + bb) * C_) * PLANE3;
    const int lane = tid & 31, wid = tid >> 5;
    const int wm = wid & 3, wn = wid >> 2;       // warp tile: m 32 @ wm*32, n 64 @ wn*64

    // issue-task constants
    const int aRow = tid >> 2, aPc = tid & 3;          // A: rows aRow, aRow+64
    const int bRow = tid >> 4, bPc = tid & 15;         // B: rows bRow, bRow+16

    auto issueChunk = [&](int ch, int st) {
        const uint32_t sg = sb + (uint32_t)st * STAGE;
#pragma unroll
        for (int t2 = 0; t2 < 2; t2++) {
            int row = aRow + t2 * 64;
            const char* src = (const char*)g_wH
                + ((size_t)(coBase + row) * KK + (size_t)ch * CHUNK) * 2 + aPc * 16;
            cpasync16(sg + OFF_A + row * AROWB + aPc * 16, src);
        }
#pragma unroll
        for (int t2 = 0; t2 < 2; t2++) {
            int row = bRow + t2 * 16;
            int k = ch * CHUNK + row;
            int ko = g_koff[k];
            int dv = g_kdv[k];
            const unsigned short* bp = (dv == 0) ? g_xo0 : (dv == 1) ? g_xo1 : g_xo2;
            const char* src = (const char*)bp
                + (size_t)(origB + ko + nOff - dv) * 2 + bPc * 16;
            cpasync16(sg + OFF_B + row * BROWB + bPc * 16, src);
        }
    };

    float4 acc[2][8];
#pragma unroll
    for (int i = 0; i < 2; i++)
#pragma unroll
        for (int j = 0; j < 8; j++) acc[i][j] = make_float4(0.f, 0.f, 0.f, 0.f);

    // ldmatrix per-thread address bases
    const uint32_t aLd = (uint32_t)(wm * 32 + (lane & 15)) * AROWB + (uint32_t)(lane >> 4) * 16;
    const uint32_t bLd0 = (uint32_t)(lane & 15) * BROWB
                        + (uint32_t)(wn * 64 + (lane >> 4) * 8) * 2;

    auto computeStage = [&](int st) {
        const uint32_t sg = sb + (uint32_t)st * STAGE;
#pragma unroll
        for (int ks = 0; ks < 2; ks++) {
            uint32_t aH[2][4], bV[4][4];
#pragma unroll
            for (int mt = 0; mt < 2; mt++)
                ldmx4(aH[mt], sg + OFF_A + aLd + (uint32_t)(mt * 16) * AROWB + ks * 32);
#pragma unroll
            for (int bt = 0; bt < 4; bt++)
                ldmx4t(bV[bt], sg + OFF_B + bLd0 + (uint32_t)(ks * 16) * BROWB + (uint32_t)(bt * 16) * 2);
#pragma unroll
            for (int mt = 0; mt < 2; mt++)
#pragma unroll
                for (int nt = 0; nt < 8; nt++) {
                    uint32_t b0 = bV[nt >> 1][(nt & 1) * 2], b1 = bV[nt >> 1][(nt & 1) * 2 + 1];
                    mma_fp16(acc[mt][nt], aH[mt], b0, b1);
                }
        }
    };

    // ---- prologue: fill stages 0..2 ----
#pragma unroll
    for (int s = 0; s < NS - 1; s++) { issueChunk(s, s); cp_commit(); }

    // ---- main loop: 1 barrier per chunk ----
    for (int ch = 0; ch < NCHUNK; ch++) {
        cp_wait2();
        __syncthreads();
        if (ch + NS - 1 < NCHUNK) issueChunk(ch + NS - 1, (ch + NS - 1) & (NS - 1));
        cp_commit();
        computeStage(ch & (NS - 1));
    }

    // ---- epilogue: BN+ReLU fused, fp16 feas stores, fused channel-sum ----
    const int r0 = lane >> 2;
    const int cq = (lane & 3) * 2;
#pragma unroll
    for (int mt = 0; mt < 2; mt++) {
        int co0 = coBase + wm * 32 + mt * 16 + r0;
        int co1 = co0 + 8;
        float sc0 = 1.f, sh0 = 0.f, sc1 = 1.f, sh1 = 0.f;
        if (a > 0) {
            int br = a - 1;
            float v0 = var[br * C_ + co0], v1 = var[br * C_ + co1];
            sc0 = gma[br * C_ + co0] * rsqrtf(v0 + 1e-5f);
            sc1 = gma[br * C_ + co1] * rsqrtf(v1 + 1e-5f);
            sh0 = bta[br * C_ + co0] - mu[br * C_ + co0] * sc0;
            sh1 = bta[br * C_ + co1] - mu[br * C_ + co1] * sc1;
        }
        float s0 = 0.f, s1 = 0.f;    // channel partial sums (a>0)
#pragma unroll
        for (int nt = 0; nt < 8; nt++) {
            int n0 = nOff + wn * 64 + nt * 8 + cq;     // even
            if (n0 >= TN_B) continue;
            int u = n0 / H3, vv = n0 - u * H3;
            if (vv >= WO) continue;
            int p = u * WO + vv;                        // even
            float4 d = acc[mt][nt];
            if (a == 0) {
                *(float2*)&g_y0[(bb * C_ + co0) * NPB + p] = make_float2(d.x, d.y);
                *(float2*)&g_y0[(bb * C_ + co1) * NPB + p] = make_float2(d.z, d.w);
            } else {
                float f0 = fmaxf(fmaf(d.x, sc0, sh0), 0.f);
                float f1 = fmaxf(fmaf(d.y, sc0, sh0), 0.f);
                float g0 = fmaxf(fmaf(d.z, sc1, sh1), 0.f);
                float g1 = fmaxf(fmaf(d.w, sc1, sh1), 0.f);
                int fb = ((a - 1) * B_ + bb) * C_;
                *(__half2*)&g_feasH[(fb + co0) * NPB + p] = __floats2half2_rn(f0, f1);
                *(__half2*)&g_feasH[(fb + co1) * NPB + p] = __floats2half2_rn(g0, g1);
                s0 += f0 + f1;
                s1 += g0 + g1;
            }
        }
        if (a > 0) {
            s0 += __shfl_xor_sync(0xffffffffu, s0, 1);
            s0 += __shfl_xor_sync(0xffffffffu, s0, 2);
            s1 += __shfl_xor_sync(0xffffffffu, s1, 1);
            s1 += __shfl_xor_sync(0xffffffffu, s1, 2);
            if ((lane & 3) == 0) {
                atomicAdd(&g_fsum[bb * C_ + co0], s0);
                atomicAdd(&g_fsum[bb * C_ + co1], s1);
            }
        }
    }
}

// ---------------- 3) attention (GAP from fused fsum) ----------------
__global__ void att_kernel(const float* __restrict__ fc1w, const float* __restrict__ fc1b,
                           const float* __restrict__ fc2w, const float* __restrict__ fc2b) {
    __shared__ float s_w1[32 * C_];
    __shared__ float s_fs[B_ * C_];
    __shared__ float s_z[B_ * 32];
    __shared__ float s_att[B_ * 4 * C_];
    int t = threadIdx.x;

    for (int i = t; i < 32 * C_; i += 256) s_w1[i] = fc1w[i];
    for (int i = t; i < B_ * C_; i += 256)
        s_fs[i] = g_fsum[i] * (1.f / (float)NPB);
    __syncthreads();

    {   // fea_z: 64 (b,d) pairs x 4 lanes each
        int pair = t >> 2;
        int b = pair >> 5, d = pair & 31;
        int sl = t & 3;
        float s = 0.f;
        for (int c = sl; c < C_; c += 4) s += s_fs[b * C_ + c] * s_w1[d * C_ + c];
        s += __shfl_down_sync(0xffffffffu, s, 2, 4);
        s += __shfl_down_sync(0xffffffffu, s, 1, 4);
        if (sl == 0) s_z[b * 32 + d] = s + fc1b[d];
    }
    __syncthreads();

    for (int i = t; i < B_ * 4 * C_; i += 256) {
        int c = i % C_; int bm = i / C_; int m = bm % 4; int b = bm / 4;
        float s = fc2b[m * C_ + c];
        const float* wr = fc2w + (m * C_ + c) * 32;
#pragma unroll
        for (int d = 0; d < 32; d++) s += s_z[b * 32 + d] * wr[d];
        s_att[(b * 4 + m) * C_ + c] = s;
    }
    __syncthreads();

    for (int i = t; i < B_ * C_; i += 256) {
        int b = i / C_, c = i % C_;
        float a0 = s_att[(b * 4 + 0) * C_ + c];
        float a1 = s_att[(b * 4 + 1) * C_ + c];
        float a2 = s_att[(b * 4 + 2) * C_ + c];
        float a3 = s_att[(b * 4 + 3) * C_ + c];
        float mx = fmaxf(fmaxf(a0, a1), fmaxf(a2, a3));
        float e0 = expf(a0 - mx), e1 = expf(a1 - mx), e2 = expf(a2 - mx), e3 = expf(a3 - mx);
        float inv = 1.f / (e0 + e1 + e2 + e3);
        g_att[(b * 4 + 0) * C_ + c] = e0 * inv;
        g_att[(b * 4 + 1) * C_ + c] = e1 * inv;
        g_att[(b * 4 + 2) * C_ + c] = e2 * inv;
        g_att[(b * 4 + 3) * C_ + c] = e3 * inv;
    }
}

// ---------------- 4) final blend (half feas) ----------------
__global__ void final_kernel(float* __restrict__ out) {
    int idx = blockIdx.x * blockDim.x + threadIdx.x;
    const int total = B_ * C_ * NQ;
    if (idx >= total) return;
    int pq = idx % NQ;
    int bc = idx / NQ;
    int c  = bc % C_, b = bc / C_;

    float4 o = ((const float4*)&g_y0[bc * NPB])[pq];
#pragma unroll
    for (int m = 0; m < 4; m++) {
        float wm = g_att[(b * 4 + m) * C_ + c];
        uint2 fv = ((const uint2*)&g_feasH[(m * B_ * C_ + bc) * NPB])[pq];
        float2 lo = __half22float2(*(__half2*)&fv.x);
        float2 hi = __half22float2(*(__half2*)&fv.y);
        o.x = fmaf(lo.x, wm, o.x);
        o.y = fmaf(lo.y, wm, o.y);
        o.z = fmaf(hi.x, wm, o.z);
        o.w = fmaf(hi.y, wm, o.w);
    }
    ((float4*)out)[idx] = o;
}

// ---------------- launch ----------------
extern "C" void kernel_launch(void* const* d_in, const int* in_sizes, int n_in,
                              void* d_out, int out_size) {
    const float* x    = (const float*)d_in[0];
    const float* w    = (const float*)d_in[1];
    const float* gma  = (const float*)d_in[2];
    const float* bta  = (const float*)d_in[3];
    const float* mu   = (const float*)d_in[4];
    const float* var  = (const float*)d_in[5];
    const float* fc1w = (const float*)d_in[6];
    const float* fc1b = (const float*)d_in[7];
    const float* fc2w = (const float*)d_in[8];
    const float* fc2b = (const float*)d_in[9];
    float* out = (float*)d_out;

    cudaFuncSetAttribute(conv_mma_kernel,
                         cudaFuncAttributeMaxDynamicSharedMemorySize, SMEM_TOTAL);

    prep_kernel<<<(C_ * KK + 255) / 256, 256>>>(w);

    dim3 sgrid(81, C_, NA * B_);
    sample_kernel<<<sgrid, 256>>>(x);

    dim3 grid(B_ * TILES_B, C_ / TILE_M, NA);
    conv_mma_kernel<<<grid, 256, SMEM_TOTAL>>>(gma, bta, mu, var);

    att_kernel<<<1, 256>>>(fc1w, fc1b, fc2w, fc2b);
    final_kernel<<<(B_ * C_ * NQ + 255) / 256, 256>>>(out);
}

// round 9
// speedup vs baseline: 6.5569x; 1.1933x over previous
#include <cuda_runtime.h>
#include <cuda_fp16.h>
#include <cstdint>

// ---------------- problem constants ----------------
constexpr int B_   = 2;
constexpr int C_   = 256;
constexpr int Hh   = 48;
constexpr int Ww   = 48;
constexpr int H3   = 144;            // 3*48 sampled grid
constexpr int HO   = 142, WO = 142;  // VALID 3x3 conv output
constexpr int NPB  = HO * WO;        // 20164
constexpr int KK   = C_ * 9;         // 2304
constexpr int PLANE3 = H3 * H3;      // 20736
constexpr int NA   = 5;              // angles
constexpr int NQ   = NPB / 4;        // 5041
constexpr int TOTXO = NA * B_ * C_ * PLANE3;   // 53,084,160
constexpr int PADE  = 8192;                    // OOB-read padding

// conv-GEMM tiling: n' = u*144 + v over full-width rows (v in [0,144), discard v>=142)
constexpr int TN_B    = HO * H3;     // 20448 n' per batch
constexpr int TILES_B = 160;         // ceil(20448/128)
constexpr int TILE_M  = 128;
constexpr int TILE_N  = 128;
constexpr int CHUNK   = 32;          // k per chunk (2 ksteps of 16)
constexpr int NCHUNK  = KK / CHUNK;  // 72
constexpr int NS      = 4;           // pipeline stages

// smem per stage: A = 128 rows x 80B, B = 32 k-rows x 272B
constexpr int AROWB = 80;
constexpr int BROWB = 272;
constexpr int OFF_A = 0;
constexpr int OFF_B = 128 * AROWB;                 // 10240
constexpr int STAGE = OFF_B + 32 * BROWB;          // 18944
constexpr int SMEM_TOTAL = NS * STAGE;             // 75776

// att kernel smem: fc1w 8192 + fc2w^T 32768 + fs 512 + z 64 + att 2048 floats
constexpr int ATT_SMEM = (8192 + 32768 + 512 + 64 + 2048) * 4;  // 174336

// ---------------- static scratch ----------------
__device__ __align__(16) unsigned short g_xo0[TOTXO + PADE];  // fp16 sampled, shift 0
__device__ __align__(16) unsigned short g_xo1[TOTXO + PADE];  // shift 1: g_xo1[i] = V[i+1]
__device__ __align__(16) unsigned short g_xo2[TOTXO + PADE];  // shift 2: g_xo2[i] = V[i+2]
__device__ __align__(16) unsigned short g_wH[C_ * KK];        // fp16 weights
__device__ __align__(16) __half g_y0H[B_ * C_ * NPB];         // fp16 identity branch
__device__ __align__(16) __half g_feasH[4 * B_ * C_ * NPB];   // fp16 BN+ReLU branches
__device__ float g_fsum[B_ * C_];
__device__ float g_att[B_ * 4 * C_];

// ---------------- angle offset tables ----------------
#define S2  1.4142135623730951
#define S2H 0.7071067811865476
// general (fractional) tables, all 5 angles
__constant__ float c_ox[45] = {
    0.f,0.f,0.f,0.f,0.f,0.f,0.f,0.f,0.f,
    (float)(1.0-S2), (float)(1.0-S2H), 1.f, (float)(-S2H), 0.f, (float)(S2H),
    -1.f, (float)(S2H-1.0), (float)(S2-1.0),
    0.f,1.f,2.f,-1.f,0.f,1.f,-2.f,-1.f,0.f,
    1.f, (float)(1.0+S2H), (float)(1.0+S2), (float)(-S2H), 0.f, (float)(S2H),
    (float)(-1.0-S2), (float)(-1.0-S2H), -1.f,
    2.f,2.f,2.f,0.f,0.f,0.f,-2.f,-2.f,-2.f
};
__constant__ float c_oy[45] = {
    0.f,0.f,0.f,0.f,0.f,0.f,0.f,0.f,0.f,
    1.f, (float)(S2H), (float)(S2-1.0), (float)(1.0-S2H), 0.f, (float)(S2H-1.0),
    (float)(1.0-S2), (float)(-S2H), -1.f,
    2.f,1.f,0.f,1.f,0.f,-1.f,0.f,-1.f,-2.f,
    (float)(1.0+S2), (float)(S2H), -1.f, (float)(1.0+S2H), 0.f, (float)(-1.0-S2H),
    1.f, (float)(-S2H), (float)(1.0+S2),
    2.f,0.f,-2.f,2.f,0.f,-2.f,2.f,0.f,-2.f
};
// integer tables for angles 0 (ia=0), 90 (ia=1), 180 (ia=2)
__constant__ int c_oxi[27] = {
    0,0,0,0,0,0,0,0,0,
    0,1,2,-1,0,1,-2,-1,0,
    2,2,2,0,0,0,-2,-2,-2
};
__constant__ int c_oyi[27] = {
    0,0,0,0,0,0,0,0,0,
    2,1,0,1,0,-1,0,-1,-2,
    2,0,-2,2,0,-2,2,0,-2
};

// ---------------- helpers ----------------
__device__ __forceinline__ uint32_t smem_u32(const void* p) {
    uint32_t a;
    asm("{ .reg .u64 t; cvta.to.shared.u64 t, %1; cvt.u32.u64 %0, t; }" : "=r"(a) : "l"(p));
    return a;
}
__device__ __forceinline__ void cpasync16(uint32_t dst, const void* src) {
    asm volatile("cp.async.cg.shared.global [%0], [%1], 16;" :: "r"(dst), "l"(src));
}
__device__ __forceinline__ void cp_commit() {
    asm volatile("cp.async.commit_group;" ::: "memory");
}
__device__ __forceinline__ void cp_wait2() {
    asm volatile("cp.async.wait_group %0;" :: "n"(2) : "memory");
}
__device__ __forceinline__ void ldmx4(uint32_t* r, uint32_t addr) {
    asm volatile("ldmatrix.sync.aligned.m8n8.x4.shared.b16 {%0,%1,%2,%3}, [%4];"
                 : "=r"(r[0]), "=r"(r[1]), "=r"(r[2]), "=r"(r[3]) : "r"(addr));
}
__device__ __forceinline__ void ldmx4t(uint32_t* r, uint32_t addr) {
    asm volatile("ldmatrix.sync.aligned.m8n8.x4.trans.shared.b16 {%0,%1,%2,%3}, [%4];"
                 : "=r"(r[0]), "=r"(r[1]), "=r"(r[2]), "=r"(r[3]) : "r"(addr));
}
__device__ __forceinline__ void mma_fp16(float4& d, const uint32_t a[4], uint32_t b0, uint32_t b1) {
    asm volatile("mma.sync.aligned.m16n8k16.row.col.f32.f16.f16.f32 "
                 "{%0,%1,%2,%3}, {%4,%5,%6,%7}, {%8,%9}, {%0,%1,%2,%3};"
                 : "+f"(d.x), "+f"(d.y), "+f"(d.z), "+f"(d.w)
                 : "r"(a[0]), "r"(a[1]), "r"(a[2]), "r"(a[3]), "r"(b0), "r"(b1));
}

// ---------------- 0) prep: fp16 weights + fsum zero ----------------
__global__ void prep_kernel(const float* __restrict__ w) {
    int i = blockIdx.x * blockDim.x + threadIdx.x;
    if (i < B_ * C_) g_fsum[i] = 0.f;
    if (i < C_ * KK) g_wH[i] = __half_as_ushort(__float2half_rn(w[i]));
}

// ---------------- 1) bilinear resample -> fp16, 3 shifted copies ----------------
// grid: (81, C_, NA*B_), block 256; 81*256 == PLANE3
__global__ void sample_kernel(const float* __restrict__ x) {
    int ip = blockIdx.x * 256 + threadIdx.x;     // in-plane index < 20736
    int c  = blockIdx.y;
    int ab = blockIdx.z;                          // a*B_ + bb
    int a  = ab >> 1, bb = ab & 1;

    int r  = ip / H3;
    int cc = ip - r * H3;

    int i = r / 3, ki = r - i * 3;
    int j = cc / 3, kj = cc - j * 3;
    int k = ki * 3 + kj;

    const float* xp = x + (bb * C_ + c) * (Hh * Ww);
    float v;

    if ((a & 1) == 0) {
        // integer-offset angles (0, 90, 180): exact point lookup
        int ia = a >> 1;
        int px = i + ki + c_oxi[ia * 9 + k];   // (i+1) + (ki-1) + ox
        int py = j + kj + c_oyi[ia * 9 + k];
        v = (px >= 1 && px <= Hh && py >= 1 && py <= Ww)
            ? xp[(px - 1) * Ww + (py - 1)] : 0.f;
    } else {
        float sx = (float)(ki - 1) + c_ox[a * 9 + k];
        float sy = (float)(kj - 1) + c_oy[a * 9 + k];
        float px = (float)(i + 1) + sx;
        float py = (float)(j + 1) + sy;

        float fx = floorf(px), fy = floorf(py);
        const float HI = 49.f;
        float ltx = fminf(fmaxf(fx,       0.f), HI);
        float lty = fminf(fmaxf(fy,       0.f), HI);
        float rbx = fminf(fmaxf(fx + 1.f, 0.f), HI);
        float rby = fminf(fmaxf(fy + 1.f, 0.f), HI);
        float pxc = fminf(fmaxf(px,       0.f), HI);
        float pyc = fminf(fmaxf(py,       0.f), HI);

        float g_lt = (1.f + (ltx - pxc)) * (1.f + (lty - pyc));
        float g_rb = (1.f - (rbx - pxc)) * (1.f - (rby - pyc));
        float g_lb = (1.f + (ltx - pxc)) * (1.f - (rby - pyc));
        float g_rt = (1.f - (rbx - pxc)) * (1.f + (lty - pyc));

        int ix0 = (int)ltx, iy0 = (int)lty, ix1 = (int)rbx, iy1 = (int)rby;

        auto gat = [&](int ix, int iy) -> float {
            ix -= 1; iy -= 1;
            if (ix < 0 || ix >= Hh || iy < 0 || iy >= Ww) return 0.f;
            return xp[ix * Ww + iy];
        };

        v = g_lt * gat(ix0, iy0) + g_rb * gat(ix1, iy1)
          + g_lb * gat(ix0, iy1) + g_rt * gat(ix1, iy0);
    }

    unsigned short h = __half_as_ushort(__float2half_rn(v));
    int idx = (ab * C_ + c) * PLANE3 + ip;
    g_xo0[idx] = h;
    if (idx >= 1) g_xo1[idx - 1] = h;
    if (idx >= 2) g_xo2[idx - 2] = h;
}

// ---------------- 2) mma.sync fp16 1-pass implicit-GEMM conv + fused BN/ReLU + fused GAP ----------------
__global__ void __launch_bounds__(256)
conv_mma_kernel(const float* __restrict__ gma, const float* __restrict__ bta,
                const float* __restrict__ mu,  const float* __restrict__ var) {
    extern __shared__ char smem[];
    const uint32_t sb = smem_u32(smem);
    const int tid = threadIdx.x;
    const int a  = blockIdx.z;
    const int coBase = blockIdx.y * TILE_M;
    const int bb  = blockIdx.x / TILES_B;
    const int tIn = blockIdx.x - bb * TILES_B;
    const int nOff = tIn * TILE_N;               // n' base within batch
    const int origB = ((a * B_ + bb) * C_) * PLANE3;
    const int lane = tid & 31, wid = tid >> 5;
    const int wm = wid & 3, wn = wid >> 2;       // warp tile: m 32 @ wm*32, n 64 @ wn*64

    // issue-task constants
    const int aRow = tid >> 2, aPc = tid & 3;          // A: rows aRow, aRow+64
    const int bRow = tid >> 4, bPc = tid & 15;         // B: rows bRow, bRow+16

    auto issueChunk = [&](int ch, int st) {
        const uint32_t sg = sb + (uint32_t)st * STAGE;
#pragma unroll
        for (int t2 = 0; t2 < 2; t2++) {
            int row = aRow + t2 * 64;
            const char* src = (const char*)g_wH
                + ((size_t)(coBase + row) * KK + (size_t)ch * CHUNK) * 2 + aPc * 16;
            cpasync16(sg + OFF_A + row * AROWB + aPc * 16, src);
        }
#pragma unroll
        for (int t2 = 0; t2 < 2; t2++) {
            int row = bRow + t2 * 16;
            int k = ch * CHUNK + row;
            int ci = k / 9;
            int r9 = k - ci * 9;
            int krow = r9 / 3;
            int dv = r9 - krow * 3;
            const unsigned short* bp = (dv == 0) ? g_xo0 : (dv == 1) ? g_xo1 : g_xo2;
            const char* src = (const char*)bp
                + (size_t)(origB + ci * PLANE3 + krow * H3 + nOff) * 2 + bPc * 16;
            cpasync16(sg + OFF_B + row * BROWB + bPc * 16, src);
        }
    };

    float4 acc[2][8];
#pragma unroll
    for (int i = 0; i < 2; i++)
#pragma unroll
        for (int j = 0; j < 8; j++) acc[i][j] = make_float4(0.f, 0.f, 0.f, 0.f);

    // ldmatrix per-thread address bases
    const uint32_t aLd = (uint32_t)(wm * 32 + (lane & 15)) * AROWB + (uint32_t)(lane >> 4) * 16;
    const uint32_t bLd0 = (uint32_t)(lane & 15) * BROWB
                        + (uint32_t)(wn * 64 + (lane >> 4) * 8) * 2;

    auto computeStage = [&](int st) {
        const uint32_t sg = sb + (uint32_t)st * STAGE;
#pragma unroll
        for (int ks = 0; ks < 2; ks++) {
            uint32_t aH[2][4], bV[4][4];
#pragma unroll
            for (int mt = 0; mt < 2; mt++)
                ldmx4(aH[mt], sg + OFF_A + aLd + (uint32_t)(mt * 16) * AROWB + ks * 32);
#pragma unroll
            for (int bt = 0; bt < 4; bt++)
                ldmx4t(bV[bt], sg + OFF_B + bLd0 + (uint32_t)(ks * 16) * BROWB + (uint32_t)(bt * 16) * 2);
#pragma unroll
            for (int mt = 0; mt < 2; mt++)
#pragma unroll
                for (int nt = 0; nt < 8; nt++) {
                    uint32_t b0 = bV[nt >> 1][(nt & 1) * 2], b1 = bV[nt >> 1][(nt & 1) * 2 + 1];
                    mma_fp16(acc[mt][nt], aH[mt], b0, b1);
                }
        }
    };

    // ---- prologue: fill stages 0..2 ----
#pragma unroll
    for (int s = 0; s < NS - 1; s++) { issueChunk(s, s); cp_commit(); }

    // ---- main loop: 1 barrier per chunk ----
    for (int ch = 0; ch < NCHUNK; ch++) {
        cp_wait2();
        __syncthreads();
        if (ch + NS - 1 < NCHUNK) issueChunk(ch + NS - 1, (ch + NS - 1) & (NS - 1));
        cp_commit();
        computeStage(ch & (NS - 1));
    }

    // ---- epilogue: BN+ReLU fused, fp16 stores, fused channel-sum ----
    const int r0 = lane >> 2;
    const int cq = (lane & 3) * 2;
#pragma unroll
    for (int mt = 0; mt < 2; mt++) {
        int co0 = coBase + wm * 32 + mt * 16 + r0;
        int co1 = co0 + 8;
        float sc0 = 1.f, sh0 = 0.f, sc1 = 1.f, sh1 = 0.f;
        if (a > 0) {
            int br = a - 1;
            float v0 = var[br * C_ + co0], v1 = var[br * C_ + co1];
            sc0 = gma[br * C_ + co0] * rsqrtf(v0 + 1e-5f);
            sc1 = gma[br * C_ + co1] * rsqrtf(v1 + 1e-5f);
            sh0 = bta[br * C_ + co0] - mu[br * C_ + co0] * sc0;
            sh1 = bta[br * C_ + co1] - mu[br * C_ + co1] * sc1;
        }
        float s0 = 0.f, s1 = 0.f;    // channel partial sums (a>0)
#pragma unroll
        for (int nt = 0; nt < 8; nt++) {
            int n0 = nOff + wn * 64 + nt * 8 + cq;     // even
            if (n0 >= TN_B) continue;
            int u = n0 / H3, vv = n0 - u * H3;
            if (vv >= WO) continue;
            int p = u * WO + vv;                        // even
            float4 d = acc[mt][nt];
            if (a == 0) {
                *(__half2*)&g_y0H[(bb * C_ + co0) * NPB + p] = __floats2half2_rn(d.x, d.y);
                *(__half2*)&g_y0H[(bb * C_ + co1) * NPB + p] = __floats2half2_rn(d.z, d.w);
            } else {
                float f0 = fmaxf(fmaf(d.x, sc0, sh0), 0.f);
                float f1 = fmaxf(fmaf(d.y, sc0, sh0), 0.f);
                float g0 = fmaxf(fmaf(d.z, sc1, sh1), 0.f);
                float g1 = fmaxf(fmaf(d.w, sc1, sh1), 0.f);
                int fb = ((a - 1) * B_ + bb) * C_;
                *(__half2*)&g_feasH[(fb + co0) * NPB + p] = __floats2half2_rn(f0, f1);
                *(__half2*)&g_feasH[(fb + co1) * NPB + p] = __floats2half2_rn(g0, g1);
                s0 += f0 + f1;
                s1 += g0 + g1;
            }
        }
        if (a > 0) {
            s0 += __shfl_xor_sync(0xffffffffu, s0, 1);
            s0 += __shfl_xor_sync(0xffffffffu, s0, 2);
            s1 += __shfl_xor_sync(0xffffffffu, s1, 1);
            s1 += __shfl_xor_sync(0xffffffffu, s1, 2);
            if ((lane & 3) == 0) {
                atomicAdd(&g_fsum[bb * C_ + co0], s0);
                atomicAdd(&g_fsum[bb * C_ + co1], s1);
            }
        }
    }
}

// ---------------- 3) attention: smem-staged weights, 1024 threads ----------------
__global__ void __launch_bounds__(1024)
att_kernel(const float* __restrict__ fc1w, const float* __restrict__ fc1b,
           const float* __restrict__ fc2w, const float* __restrict__ fc2b) {
    extern __shared__ float sm[];
    float* sW1  = sm;                  // [32*256]  fc1 weights
    float* sW2  = sm + 8192;           // [32][1024] fc2 weights TRANSPOSED: sW2[d*1024 + (m*C+c)]
    float* sFs  = sm + 8192 + 32768;   // [512]
    float* sZ   = sFs + 512;           // [64]
    float* sAtt = sZ + 64;             // [2048]
    int t = threadIdx.x;

    // stage weights (vectorized) + fea_s
#pragma unroll
    for (int i = 0; i < 2; i++)
        ((float4*)sW1)[t + i * 1024] = ((const float4*)fc1w)[t + i * 1024];
#pragma unroll
    for (int i = 0; i < 8; i++) {
        int v4 = t + i * 1024;           // fc2w float4 index; covers 32768 floats
        float4 w4 = ((const float4*)fc2w)[v4];
        int mc = v4 >> 3;                // (m*C+c) in [0,1024), 8 float4 per mc row
        int d0 = (v4 & 7) * 4;
        sW2[(d0 + 0) * 1024 + mc] = w4.x;
        sW2[(d0 + 1) * 1024 + mc] = w4.y;
        sW2[(d0 + 2) * 1024 + mc] = w4.z;
        sW2[(d0 + 3) * 1024 + mc] = w4.w;
    }
    if (t < B_ * C_) sFs[t] = g_fsum[t] * (1.f / (float)NPB);
    __syncthreads();

    {   // fea_z: 64 (b,d) pairs x 16 lanes each
        int pair = t >> 4;
        int b = pair >> 5, d = pair & 31;
        int sl = t & 15;
        float s = 0.f;
#pragma unroll
        for (int c = sl; c < C_; c += 16) s += sFs[b * C_ + c] * sW1[d * C_ + c];
        s += __shfl_down_sync(0xffffffffu, s, 8, 16);
        s += __shfl_down_sync(0xffffffffu, s, 4, 16);
        s += __shfl_down_sync(0xffffffffu, s, 2, 16);
        s += __shfl_down_sync(0xffffffffu, s, 1, 16);
        if (sl == 0) sZ[b * 32 + d] = s + fc1b[d];
    }
    __syncthreads();

#pragma unroll
    for (int i = 0; i < 2; i++) {     // att logits: 2048 outputs (b in [0,2), mc in [0,1024))
        int o = t + i * 1024;
        int b = o >> 10;
        int mc = o & 1023;            // m*256 + c
        float s = fc2b[mc];
#pragma unroll
        for (int d = 0; d < 32; d++) s += sZ[b * 32 + d] * sW2[d * 1024 + mc];
        sAtt[b * 1024 + mc] = s;
    }
    __syncthreads();

    if (t < B_ * C_) {                // softmax over m
        int b = t >> 8, c = t & 255;
        float a0 = sAtt[b * 1024 + 0 * C_ + c];
        float a1 = sAtt[b * 1024 + 1 * C_ + c];
        float a2 = sAtt[b * 1024 + 2 * C_ + c];
        float a3 = sAtt[b * 1024 + 3 * C_ + c];
        float mx = fmaxf(fmaxf(a0, a1), fmaxf(a2, a3));
        float e0 = expf(a0 - mx), e1 = expf(a1 - mx), e2 = expf(a2 - mx), e3 = expf(a3 - mx);
        float inv = 1.f / (e0 + e1 + e2 + e3);
        g_att[(b * 4 + 0) * C_ + c] = e0 * inv;
        g_att[(b * 4 + 1) * C_ + c] = e1 * inv;
        g_att[(b * 4 + 2) * C_ + c] = e2 * inv;
        g_att[(b * 4 + 3) * C_ + c] = e3 * inv;
    }
}

// ---------------- 4) final blend (half y0 + half feas) ----------------
__global__ void final_kernel(float* __restrict__ out) {
    int idx = blockIdx.x * blockDim.x + threadIdx.x;
    const int total = B_ * C_ * NQ;
    if (idx >= total) return;
    int pq = idx % NQ;
    int bc = idx / NQ;
    int c  = bc % C_, b = bc / C_;

    uint2 yv = ((const uint2*)&g_y0H[bc * NPB])[pq];
    float2 ylo = __half22float2(*(__half2*)&yv.x);
    float2 yhi = __half22float2(*(__half2*)&yv.y);
    float4 o = make_float4(ylo.x, ylo.y, yhi.x, yhi.y);
#pragma unroll
    for (int m = 0; m < 4; m++) {
        float wm = g_att[(b * 4 + m) * C_ + c];
        uint2 fv = ((const uint2*)&g_feasH[(m * B_ * C_ + bc) * NPB])[pq];
        float2 lo = __half22float2(*(__half2*)&fv.x);
        float2 hi = __half22float2(*(__half2*)&fv.y);
        o.x = fmaf(lo.x, wm, o.x);
        o.y = fmaf(lo.y, wm, o.y);
        o.z = fmaf(hi.x, wm, o.z);
        o.w = fmaf(hi.y, wm, o.w);
    }
    ((float4*)out)[idx] = o;
}

// ---------------- launch ----------------
extern "C" void kernel_launch(void* const* d_in, const int* in_sizes, int n_in,
                              void* d_out, int out_size) {
    const float* x    = (const float*)d_in[0];
    const float* w    = (const float*)d_in[1];
    const float* gma  = (const float*)d_in[2];
    const float* bta  = (const float*)d_in[3];
    const float* mu   = (const float*)d_in[4];
    const float* var  = (const float*)d_in[5];
    const float* fc1w = (const float*)d_in[6];
    const float* fc1b = (const float*)d_in[7];
    const float* fc2w = (const float*)d_in[8];
    const float* fc2b = (const float*)d_in[9];
    float* out = (float*)d_out;

    cudaFuncSetAttribute(conv_mma_kernel,
                         cudaFuncAttributeMaxDynamicSharedMemorySize, SMEM_TOTAL);
    cudaFuncSetAttribute(att_kernel,
                         cudaFuncAttributeMaxDynamicSharedMemorySize, ATT_SMEM);

    prep_kernel<<<(C_ * KK + 255) / 256, 256>>>(w);

    dim3 sgrid(81, C_, NA * B_);
    sample_kernel<<<sgrid, 256>>>(x);

    dim3 grid(B_ * TILES_B, C_ / TILE_M, NA);
    conv_mma_kernel<<<grid, 256, SMEM_TOTAL>>>(gma, bta, mu, var);

    att_kernel<<<1, 1024, ATT_SMEM>>>(fc1w, fc1b, fc2w, fc2b);
    final_kernel<<<(B_ * C_ * NQ + 255) / 256, 256>>>(out);
}